// round 6
// baseline (speedup 1.0000x reference)
#include <cuda_runtime.h>
#include <math.h>
#include <stdint.h>

// ---------------- problem constants ----------------
#define NN 50000         // nodes
#define NE 600000        // edges
#define HD 128           // hidden
#define NG 64            // graphs
#define K3 384           // 3*H
#define NLAYERS 2
#define NSTEPS 2

// ---------------- device scratch (no allocs allowed) ----------------
__device__ float d_h[(size_t)NN * HD];
__device__ float d_a[(size_t)NN * HD];
__device__ int   d_cnt[NN];
__device__ int   d_rowptr[NN + 1];
__device__ int   d_cursor[NN];
__device__ int   d_edges[NE];
__device__ int   d_goff[NG + 1];
__device__ float d_wcatT[2 * HD * K3];   // per layer: [128 out][384 k]
__device__ float d_agg[NG * K3];

__device__ __forceinline__ unsigned cvt_tf32(float x) {
    unsigned r;
    asm("cvt.rna.tf32.f32 %0, %1;" : "=r"(r) : "f"(x));
    return r;
}

__device__ __forceinline__ void f4add(float4& a, const float4& b) {
    a.x += b.x; a.y += b.y; a.z += b.z; a.w += b.w;
}

// ---------------- small setup kernels ----------------

// WcatT[l][o][t*128+h] = Wl[l][t][h][o]
__global__ void transpose_wl_kernel(const float* __restrict__ Wl, float* __restrict__ wcatT) {
    int idx = blockIdx.x * blockDim.x + threadIdx.x;
    if (idx >= 2 * 3 * 128 * 128) return;
    int o  = idx & 127;
    int hh = (idx >> 7) & 127;
    int lt = idx >> 14;
    int t  = lt % 3;
    int l  = lt / 3;
    wcatT[(size_t)l * HD * K3 + (size_t)o * K3 + t * 128 + hh] = Wl[idx];
}

__global__ void count_edges_kernel(const int* __restrict__ dst, int* __restrict__ cnt) {
    int e = blockIdx.x * blockDim.x + threadIdx.x;
    if (e < NE) atomicAdd(&cnt[dst[e]], 1);
}

// single-block scan with carry -> rowptr (exclusive, +1 shifted) and cursor
__global__ void scan_counts_kernel(const int* __restrict__ cnt, int* __restrict__ rowptr,
                                   int* __restrict__ cursor, int n) {
    __shared__ int sh[1024];
    __shared__ int carry;
    int tid = threadIdx.x;
    if (tid == 0) { carry = 0; rowptr[0] = 0; }
    __syncthreads();
    for (int base = 0; base < n; base += 1024) {
        int i = base + tid;
        int v = (i < n) ? cnt[i] : 0;
        sh[tid] = v;
        __syncthreads();
        for (int off = 1; off < 1024; off <<= 1) {
            int t = (tid >= off) ? sh[tid - off] : 0;
            __syncthreads();
            sh[tid] += t;
            __syncthreads();
        }
        int incl = sh[tid];
        int c = carry;
        if (i < n) {
            rowptr[i + 1] = c + incl;
            cursor[i]     = c + incl - v;
        }
        __syncthreads();
        if (tid == 1023) carry = c + sh[1023];
        __syncthreads();
    }
}

__global__ void place_edges_kernel(const int* __restrict__ src, const int* __restrict__ dst,
                                   const int* __restrict__ etype, int* __restrict__ cursor,
                                   int* __restrict__ edges) {
    int e = blockIdx.x * blockDim.x + threadIdx.x;
    if (e >= NE) return;
    int d = dst[e];
    int pos = atomicAdd(&cursor[d], 1);
    edges[pos] = src[e] | (etype[e] << 24);
}

__global__ void goff_kernel(const int* __restrict__ graph_id, int* __restrict__ goff) {
    int g = threadIdx.x;
    if (g > NG) return;
    if (g == NG) { goff[NG] = NN; return; }
    int lo = 0, hi = NN;
    while (lo < hi) {
        int mid = (lo + hi) >> 1;
        if (graph_id[mid] < g) lo = mid + 1; else hi = mid;
    }
    goff[g] = lo;
}

__global__ void embed_kernel(const int* __restrict__ text_idx, const float* __restrict__ emb,
                             float* __restrict__ h) {
    int idx = blockIdx.x * blockDim.x + threadIdx.x;
    if (idx >= NN * HD) return;
    int n = idx >> 7, c = idx & 127;
    h[idx] = emb[(size_t)text_idx[n] * HD + c];
}

__global__ void mean_kernel(const float* __restrict__ h, const int* __restrict__ goff,
                            float* __restrict__ agg, int slot) {
    int g = blockIdx.x;
    int c = threadIdx.x; // 128
    int s = goff[g], e = goff[g + 1];
    float a0 = 0.f, a1 = 0.f, a2 = 0.f, a3 = 0.f;
    int r = s;
    for (; r + 4 <= e; r += 4) {
        a0 += h[(size_t)(r + 0) * HD + c];
        a1 += h[(size_t)(r + 1) * HD + c];
        a2 += h[(size_t)(r + 2) * HD + c];
        a3 += h[(size_t)(r + 3) * HD + c];
    }
    for (; r < e; ++r) a0 += h[(size_t)r * HD + c];
    float acc = (a0 + a1) + (a2 + a3);
    float cntf = (float)((e - s) > 0 ? (e - s) : 1);
    agg[g * K3 + slot * HD + c] = acc / cntf;
}

// ================= fused message-pass kernel (aggregate + per-etype linear) =============
// Block = 128 dst rows. For each etype chunk t: gather sum_{e:type t} h[src] into smem
// (tf32), load W chunk (128x128, tf32) into smem, MMA-accumulate over K. Epilogue adds
// deg-weighted per-etype bias and writes a[m][0..127].
// smem: Ag[128][132] u32, Bg[128][132] u32, degS[3][128] f32  = 136704 B
#define MP1_SMEM ((2 * 128 * 132 + 3 * 128) * 4)

__global__ __launch_bounds__(512) void mp1_kernel(
    const float* __restrict__ h, const int* __restrict__ rowptr,
    const int* __restrict__ edges, const float* __restrict__ wcatT_l,
    const float* __restrict__ bl3, float* __restrict__ a_out)
{
    extern __shared__ unsigned smu[];
    unsigned* Agu  = smu;                      // [128][132]
    unsigned* Bgu  = smu + 128 * 132;          // [128][132]
    float*    degS = (float*)(smu + 2 * 128 * 132);  // [3][128]

    const int tid  = threadIdx.x;
    const int warp = tid >> 5;
    const int lane = tid & 31;
    const int g    = lane >> 2;
    const int tg   = lane & 3;
    const int wm   = (warp >> 2) * 32;   // 0,32,64,96
    const int wn   = (warp & 3) * 32;    // 0,32,64,96
    const int m0   = blockIdx.x * 128;

    float acc[2][4][4];
#pragma unroll
    for (int mi = 0; mi < 2; ++mi)
#pragma unroll
        for (int ni = 0; ni < 4; ++ni)
#pragma unroll
            for (int q = 0; q < 4; ++q) acc[mi][ni][q] = 0.f;

    const float4* h4 = (const float4*)h;

    for (int t = 0; t < 3; ++t) {
        __syncthreads();   // previous chunk's MMA reads done
        // ---- gather: 16 warps x 8 rows ----
#pragma unroll
        for (int rr = 0; rr < 8; ++rr) {
            int row = warp * 8 + rr;
            int m = m0 + row;
            float4 s = make_float4(0.f, 0.f, 0.f, 0.f);
            int cnt = 0;
            if (m < NN) {
                int i = rowptr[m], e1 = rowptr[m + 1];
                for (; i + 2 <= e1; i += 2) {
                    int p0 = edges[i], p1 = edges[i + 1];
                    if ((p0 >> 24) == t) { f4add(s, h4[(size_t)(p0 & 0xFFFFFF) * 32 + lane]); cnt++; }
                    if ((p1 >> 24) == t) { f4add(s, h4[(size_t)(p1 & 0xFFFFFF) * 32 + lane]); cnt++; }
                }
                for (; i < e1; ++i) {
                    int p = edges[i];
                    if ((p >> 24) == t) { f4add(s, h4[(size_t)(p & 0xFFFFFF) * 32 + lane]); cnt++; }
                }
            }
            int o = row * 132 + lane * 4;
            Agu[o + 0] = cvt_tf32(s.x);
            Agu[o + 1] = cvt_tf32(s.y);
            Agu[o + 2] = cvt_tf32(s.z);
            Agu[o + 3] = cvt_tf32(s.w);
            if (lane == 0) degS[t * 128 + row] = (float)cnt;
        }
        // ---- load W chunk: rows j 0..127, k local 0..127 (global k = t*128+k) ----
#pragma unroll
        for (int u = 0; u < 8; ++u) {
            int f = tid + u * 512;           // 0..4095 float4 units
            int r = f >> 5;                  // 32 float4 per row
            int q = (f & 31) << 2;
            const float* sp = wcatT_l + (size_t)r * K3 + t * 128 + q;
            int o = r * 132 + q;
            Bgu[o + 0] = cvt_tf32(sp[0]);
            Bgu[o + 1] = cvt_tf32(sp[1]);
            Bgu[o + 2] = cvt_tf32(sp[2]);
            Bgu[o + 3] = cvt_tf32(sp[3]);
        }
        __syncthreads();
        // ---- MMA over this chunk (16 k8 steps) ----
#pragma unroll
        for (int kk = 0; kk < 128; kk += 8) {
            unsigned af[2][4], bf[4][2];
#pragma unroll
            for (int mi = 0; mi < 2; ++mi) {
                int r = wm + mi * 16 + g;
                af[mi][0] = Agu[r * 132 + kk + tg];
                af[mi][1] = Agu[(r + 8) * 132 + kk + tg];
                af[mi][2] = Agu[r * 132 + kk + tg + 4];
                af[mi][3] = Agu[(r + 8) * 132 + kk + tg + 4];
            }
#pragma unroll
            for (int ni = 0; ni < 4; ++ni) {
                int c = wn + ni * 8 + g;
                bf[ni][0] = Bgu[c * 132 + kk + tg];
                bf[ni][1] = Bgu[c * 132 + kk + tg + 4];
            }
#pragma unroll
            for (int mi = 0; mi < 2; ++mi)
#pragma unroll
                for (int ni = 0; ni < 4; ++ni) {
                    asm volatile(
                        "mma.sync.aligned.m16n8k8.row.col.f32.tf32.tf32.f32 "
                        "{%0,%1,%2,%3}, {%4,%5,%6,%7}, {%8,%9}, {%0,%1,%2,%3};"
                        : "+f"(acc[mi][ni][0]), "+f"(acc[mi][ni][1]),
                          "+f"(acc[mi][ni][2]), "+f"(acc[mi][ni][3])
                        : "r"(af[mi][0]), "r"(af[mi][1]), "r"(af[mi][2]), "r"(af[mi][3]),
                          "r"(bf[ni][0]), "r"(bf[ni][1]));
                }
        }
    }

    // ---- epilogue: + deg-weighted etype bias, write a ----
#pragma unroll
    for (int mi = 0; mi < 2; ++mi) {
        int r0l = wm + mi * 16 + g;
        int r1l = r0l + 8;
        int gm0 = m0 + r0l, gm1 = m0 + r1l;
        float d00 = degS[r0l], d01 = degS[128 + r0l], d02 = degS[256 + r0l];
        float d10 = degS[r1l], d11 = degS[128 + r1l], d12 = degS[256 + r1l];
#pragma unroll
        for (int ni = 0; ni < 4; ++ni) {
            int c = wn + ni * 8 + tg * 2;
            float e00 = bl3[c],       e01 = bl3[c + 1];
            float e10 = bl3[128 + c], e11 = bl3[129 + c];
            float e20 = bl3[256 + c], e21 = bl3[257 + c];
            float v00 = acc[mi][ni][0] + d00 * e00 + d01 * e10 + d02 * e20;
            float v01 = acc[mi][ni][1] + d00 * e01 + d01 * e11 + d02 * e21;
            float v10 = acc[mi][ni][2] + d10 * e00 + d11 * e10 + d12 * e20;
            float v11 = acc[mi][ni][3] + d10 * e01 + d11 * e11 + d12 * e21;
            if (gm0 < NN) *(float2*)(a_out + (size_t)gm0 * HD + c) = make_float2(v00, v01);
            if (gm1 < NN) *(float2*)(a_out + (size_t)gm1 * HD + c) = make_float2(v10, v11);
        }
    }
}

// ================= fused GRU kernel: gi/gh GEMMs + gates, h updated in place ============
// Block = 128 rows, 256 threads. Phases:
//   P1: i_n  = a @ W_ih_n^T + b  (K=128) -> smem INs
//   P2: h_n  = h @ W_hh_n^T + b  (K=128) -> smem HNs
//   P3: r    = sigmoid([a|h] @ [W_ih_r|W_hh_r]^T + b) (K=256) -> regs
//   P4: z    = sigmoid(...z...) (K=256); gates; write h
// smem: As/Bs double-buffered [2][128][36] u32 + INs/HNs [128][132] f32 = 208896 B
#define GRU_SMEM ((4 * 128 * 36 + 2 * 128 * 132) * 4)

__device__ __forceinline__ float siggy(float x) { return 1.f / (1.f + expf(-x)); }

__global__ __launch_bounds__(256) void fgru_kernel(
    const float* __restrict__ a, float* __restrict__ h,
    const float* __restrict__ W_ih_l, const float* __restrict__ W_hh_l,
    const float* __restrict__ b_ih_l, const float* __restrict__ b_hh_l)
{
    extern __shared__ unsigned smu[];
    unsigned* AsBase = smu;                       // 2 x 128 x 36
    unsigned* BsBase = smu + 2 * 128 * 36;        // 2 x 128 x 36
    float*    INs    = (float*)(smu + 4 * 128 * 36);  // 128 x 132
    float*    HNs    = INs + 128 * 132;

    const int tid  = threadIdx.x;
    const int warp = tid >> 5;
    const int lane = tid & 31;
    const int g    = lane >> 2;
    const int tg   = lane & 3;
    const int wm   = (warp >> 2) * 64;   // 0 / 64
    const int wn   = (warp & 3) * 32;    // 0..96
    const int m0   = blockIdx.x * 128;

    float acc[4][4][4];
    float rreg[4][4][4];
    float4 rA[4], rB[4];

    auto GLOAD = [&](const float* A1, const float* A2,
                     const float* B1, const float* B2, int kt) {
        const float* Asrc = (kt >= 4) ? A2 : A1;
        const float* Bsrc = (kt >= 4) ? B2 : B1;
        int kl = (kt & 3) * 32;
#pragma unroll
        for (int u = 0; u < 4; ++u) {
            int f  = tid + u * 256;
            int r  = f >> 3;
            int kq = (f & 7) << 2;
            int gm = m0 + r;
            rA[u] = (gm < NN) ? *(const float4*)(Asrc + (size_t)gm * HD + kl + kq)
                              : make_float4(0.f, 0.f, 0.f, 0.f);
            rB[u] = *(const float4*)(Bsrc + (size_t)r * HD + kl + kq);
        }
    };
    auto SSTORE = [&](int buf) {
        unsigned* as = AsBase + buf * (128 * 36);
        unsigned* bs = BsBase + buf * (128 * 36);
#pragma unroll
        for (int u = 0; u < 4; ++u) {
            int f  = tid + u * 256;
            int r  = f >> 3;
            int kq = (f & 7) << 2;
            as[r * 36 + kq + 0] = cvt_tf32(rA[u].x);
            as[r * 36 + kq + 1] = cvt_tf32(rA[u].y);
            as[r * 36 + kq + 2] = cvt_tf32(rA[u].z);
            as[r * 36 + kq + 3] = cvt_tf32(rA[u].w);
            bs[r * 36 + kq + 0] = cvt_tf32(rB[u].x);
            bs[r * 36 + kq + 1] = cvt_tf32(rB[u].y);
            bs[r * 36 + kq + 2] = cvt_tf32(rB[u].z);
            bs[r * 36 + kq + 3] = cvt_tf32(rB[u].w);
        }
    };
    auto COMP = [&](int buf) {
        const unsigned* as = AsBase + buf * (128 * 36);
        const unsigned* bs = BsBase + buf * (128 * 36);
#pragma unroll
        for (int kk = 0; kk < 32; kk += 8) {
            unsigned af[4][4], bf[4][2];
#pragma unroll
            for (int mi = 0; mi < 4; ++mi) {
                int r = wm + mi * 16 + g;
                af[mi][0] = as[r * 36 + kk + tg];
                af[mi][1] = as[(r + 8) * 36 + kk + tg];
                af[mi][2] = as[r * 36 + kk + tg + 4];
                af[mi][3] = as[(r + 8) * 36 + kk + tg + 4];
            }
#pragma unroll
            for (int ni = 0; ni < 4; ++ni) {
                int c = wn + ni * 8 + g;
                bf[ni][0] = bs[c * 36 + kk + tg];
                bf[ni][1] = bs[c * 36 + kk + tg + 4];
            }
#pragma unroll
            for (int mi = 0; mi < 4; ++mi)
#pragma unroll
                for (int ni = 0; ni < 4; ++ni) {
                    asm volatile(
                        "mma.sync.aligned.m16n8k8.row.col.f32.tf32.tf32.f32 "
                        "{%0,%1,%2,%3}, {%4,%5,%6,%7}, {%8,%9}, {%0,%1,%2,%3};"
                        : "+f"(acc[mi][ni][0]), "+f"(acc[mi][ni][1]),
                          "+f"(acc[mi][ni][2]), "+f"(acc[mi][ni][3])
                        : "r"(af[mi][0]), "r"(af[mi][1]), "r"(af[mi][2]), "r"(af[mi][3]),
                          "r"(bf[ni][0]), "r"(bf[ni][1]));
                }
        }
    };
    auto RUN = [&](const float* A1, const float* A2,
                   const float* B1, const float* B2, int numT) {
#pragma unroll
        for (int mi = 0; mi < 4; ++mi)
#pragma unroll
            for (int ni = 0; ni < 4; ++ni)
#pragma unroll
                for (int q = 0; q < 4; ++q) acc[mi][ni][q] = 0.f;
        GLOAD(A1, A2, B1, B2, 0);
        SSTORE(0);
        __syncthreads();
        for (int t = 0; t < numT; ++t) {
            if (t + 1 < numT) GLOAD(A1, A2, B1, B2, t + 1);
            COMP(t & 1);
            if (t + 1 < numT) SSTORE((t + 1) & 1);
            __syncthreads();
        }
    };

    // ---- P1: i_n ----
    RUN(a, a, W_ih_l + 256 * HD, W_ih_l + 256 * HD, 4);
#pragma unroll
    for (int mi = 0; mi < 4; ++mi) {
        int r0l = wm + mi * 16 + g, r1l = r0l + 8;
#pragma unroll
        for (int ni = 0; ni < 4; ++ni) {
            int c = wn + ni * 8 + tg * 2;
            float b0 = b_ih_l[256 + c], b1 = b_ih_l[257 + c];
            INs[r0l * 132 + c]     = acc[mi][ni][0] + b0;
            INs[r0l * 132 + c + 1] = acc[mi][ni][1] + b1;
            INs[r1l * 132 + c]     = acc[mi][ni][2] + b0;
            INs[r1l * 132 + c + 1] = acc[mi][ni][3] + b1;
        }
    }

    // ---- P2: h_n ----
    RUN(h, h, W_hh_l + 256 * HD, W_hh_l + 256 * HD, 4);
#pragma unroll
    for (int mi = 0; mi < 4; ++mi) {
        int r0l = wm + mi * 16 + g, r1l = r0l + 8;
#pragma unroll
        for (int ni = 0; ni < 4; ++ni) {
            int c = wn + ni * 8 + tg * 2;
            float b0 = b_hh_l[256 + c], b1 = b_hh_l[257 + c];
            HNs[r0l * 132 + c]     = acc[mi][ni][0] + b0;
            HNs[r0l * 132 + c + 1] = acc[mi][ni][1] + b1;
            HNs[r1l * 132 + c]     = acc[mi][ni][2] + b0;
            HNs[r1l * 132 + c + 1] = acc[mi][ni][3] + b1;
        }
    }

    // ---- P3: r gate (joint K=256 over [a|h]) ----
    RUN(a, h, W_ih_l, W_hh_l, 8);
#pragma unroll
    for (int mi = 0; mi < 4; ++mi)
#pragma unroll
        for (int ni = 0; ni < 4; ++ni) {
            int c = wn + ni * 8 + tg * 2;
            float b0 = b_ih_l[c] + b_hh_l[c];
            float b1 = b_ih_l[c + 1] + b_hh_l[c + 1];
            rreg[mi][ni][0] = siggy(acc[mi][ni][0] + b0);
            rreg[mi][ni][1] = siggy(acc[mi][ni][1] + b1);
            rreg[mi][ni][2] = siggy(acc[mi][ni][2] + b0);
            rreg[mi][ni][3] = siggy(acc[mi][ni][3] + b1);
        }

    // ---- P4: z gate + fused gates, write h ----
    RUN(a, h, W_ih_l + 128 * HD, W_hh_l + 128 * HD, 8);
#pragma unroll
    for (int mi = 0; mi < 4; ++mi) {
        int r0l = wm + mi * 16 + g, r1l = r0l + 8;
        int gm0 = m0 + r0l, gm1 = m0 + r1l;
#pragma unroll
        for (int ni = 0; ni < 4; ++ni) {
            int c = wn + ni * 8 + tg * 2;
            float b0 = b_ih_l[128 + c] + b_hh_l[128 + c];
            float b1 = b_ih_l[129 + c] + b_hh_l[129 + c];
            float z00 = siggy(acc[mi][ni][0] + b0);
            float z01 = siggy(acc[mi][ni][1] + b1);
            float z10 = siggy(acc[mi][ni][2] + b0);
            float z11 = siggy(acc[mi][ni][3] + b1);
            float nc00 = tanhf(INs[r0l * 132 + c]     + rreg[mi][ni][0] * HNs[r0l * 132 + c]);
            float nc01 = tanhf(INs[r0l * 132 + c + 1] + rreg[mi][ni][1] * HNs[r0l * 132 + c + 1]);
            float nc10 = tanhf(INs[r1l * 132 + c]     + rreg[mi][ni][2] * HNs[r1l * 132 + c]);
            float nc11 = tanhf(INs[r1l * 132 + c + 1] + rreg[mi][ni][3] * HNs[r1l * 132 + c + 1]);
            if (gm0 < NN) {
                float2 hv = *(float2*)(h + (size_t)gm0 * HD + c);
                float2 ov = make_float2((1.f - z00) * nc00 + z00 * hv.x,
                                        (1.f - z01) * nc01 + z01 * hv.y);
                *(float2*)(h + (size_t)gm0 * HD + c) = ov;
            }
            if (gm1 < NN) {
                float2 hv = *(float2*)(h + (size_t)gm1 * HD + c);
                float2 ov = make_float2((1.f - z10) * nc10 + z10 * hv.x,
                                        (1.f - z11) * nc11 + z11 * hv.y);
                *(float2*)(h + (size_t)gm1 * HD + c) = ov;
            }
        }
    }
}

// ---------------- head: x = relu(agg@W1+b1); res = x@W2+b2; emit [res | agg] ------------
__global__ void head_kernel(const float* __restrict__ agg, const float* __restrict__ W1,
                            const float* __restrict__ b1, const float* __restrict__ W2,
                            const float* __restrict__ b2, float* __restrict__ out,
                            int out_size) {
    int g = blockIdx.x;
    int o = threadIdx.x; // 128
    __shared__ float sa[K3];
    __shared__ float sx[HD];
    for (int k = o; k < K3; k += HD) sa[k] = agg[g * K3 + k];
    __syncthreads();
    float acc = b1[o];
    for (int k = 0; k < K3; ++k) acc += sa[k] * W1[k * HD + o];
    acc = fmaxf(acc, 0.f);
    sx[o] = acc * W2[o];
    __syncthreads();
    for (int st = 64; st > 0; st >>= 1) {
        if (o < st) sx[o] += sx[o + st];
        __syncthreads();
    }
    if (o == 0 && g < out_size) out[g] = sx[0] + b2[0];
    for (int k = o; k < K3; k += HD) {
        int oi = NG + g * K3 + k;
        if (oi < out_size) out[oi] = sa[k];
    }
}

// ---------------- host launch ----------------
extern "C" void kernel_launch(void* const* d_in, const int* in_sizes, int n_in,
                              void* d_out, int out_size) {
    const int*   text_idx = (const int*)d_in[0];
    const int*   src      = (const int*)d_in[1];
    const int*   dst      = (const int*)d_in[2];
    const int*   etype    = (const int*)d_in[3];
    const int*   graph_id = (const int*)d_in[4];
    const float* emb      = (const float*)d_in[5];
    const float* Wl       = (const float*)d_in[6];
    const float* bl       = (const float*)d_in[7];
    const float* W_ih     = (const float*)d_in[8];
    const float* W_hh     = (const float*)d_in[9];
    const float* b_ih     = (const float*)d_in[10];
    const float* b_hh     = (const float*)d_in[11];
    const float* W1       = (const float*)d_in[12];
    const float* b1       = (const float*)d_in[13];
    const float* W2       = (const float*)d_in[14];
    const float* b2       = (const float*)d_in[15];
    float* out = (float*)d_out;

    float *h, *a, *wcatT, *agg;
    int *cnt, *rowptr, *cursor, *edges, *goff;
    cudaGetSymbolAddress((void**)&h,      d_h);
    cudaGetSymbolAddress((void**)&a,      d_a);
    cudaGetSymbolAddress((void**)&wcatT,  d_wcatT);
    cudaGetSymbolAddress((void**)&agg,    d_agg);
    cudaGetSymbolAddress((void**)&cnt,    d_cnt);
    cudaGetSymbolAddress((void**)&rowptr, d_rowptr);
    cudaGetSymbolAddress((void**)&cursor, d_cursor);
    cudaGetSymbolAddress((void**)&edges,  d_edges);
    cudaGetSymbolAddress((void**)&goff,   d_goff);

    static bool attr_set = false;
    if (!attr_set) {
        cudaFuncSetAttribute(mp1_kernel,
                             cudaFuncAttributeMaxDynamicSharedMemorySize, MP1_SMEM);
        cudaFuncSetAttribute(fgru_kernel,
                             cudaFuncAttributeMaxDynamicSharedMemorySize, GRU_SMEM);
        attr_set = true;
    }

    // ---- graph structure + weight transpose (per launch, graph-capturable) ----
    transpose_wl_kernel<<<(2 * 3 * 128 * 128 + 255) / 256, 256>>>(Wl, wcatT);
    cudaMemsetAsync(cnt, 0, NN * sizeof(int));
    count_edges_kernel<<<(NE + 255) / 256, 256>>>(dst, cnt);
    scan_counts_kernel<<<1, 1024>>>(cnt, rowptr, cursor, NN);
    place_edges_kernel<<<(NE + 255) / 256, 256>>>(src, dst, etype, cursor, edges);
    goff_kernel<<<1, NG + 1>>>(graph_id, goff);

    embed_kernel<<<(NN * HD + 255) / 256, 256>>>(text_idx, emb, h);
    mean_kernel<<<NG, HD>>>(h, goff, agg, 0);

    const int nblk = (NN + 127) / 128;

    for (int l = 0; l < NLAYERS; ++l) {
        for (int s = 0; s < NSTEPS; ++s) {
            mp1_kernel<<<nblk, 512, MP1_SMEM>>>(
                h, rowptr, edges,
                wcatT + (size_t)l * HD * K3, bl + l * K3, a);
            fgru_kernel<<<nblk, 256, GRU_SMEM>>>(
                a, h,
                W_ih + (size_t)l * K3 * HD, W_hh + (size_t)l * K3 * HD,
                b_ih + l * K3, b_hh + l * K3);
        }
        mean_kernel<<<NG, HD>>>(h, goff, agg, l + 1);
    }

    head_kernel<<<NG, HD>>>(agg, W1, b1, W2, b2, out, out_size);
}

// round 7
// speedup vs baseline: 1.0778x; 1.0778x over previous
#include <cuda_runtime.h>
#include <math.h>
#include <stdint.h>

// ---------------- problem constants ----------------
#define NN 50000         // nodes
#define NE 600000        // edges
#define HD 128           // hidden
#define NG 64            // graphs
#define K3 384           // 3*H
#define NLAYERS 2
#define NSTEPS 2

// ---------------- device scratch (no allocs allowed) ----------------
__device__ float d_h[(size_t)NN * HD];
__device__ float d_S[(size_t)NN * K3];
__device__ float d_a[(size_t)NN * HD];
__device__ float d_gi[(size_t)NN * K3];
__device__ float d_gh[(size_t)NN * K3];
__device__ float d_deg[(size_t)NN * 3];
__device__ int   d_cnt[NN];
__device__ int   d_rowptr[NN + 1];
__device__ int   d_cursor[NN];
__device__ int   d_edges[NE];
__device__ int   d_goff[NG + 1];
__device__ float d_wcatT[2 * HD * K3];   // per layer: [128 out][384 k]
__device__ float d_agg[NG * K3];

__device__ __forceinline__ unsigned cvt_tf32(float x) {
    unsigned r;
    asm("cvt.rna.tf32.f32 %0, %1;" : "=r"(r) : "f"(x));
    return r;
}

__device__ __forceinline__ void f4add(float4& a, const float4& b) {
    a.x += b.x; a.y += b.y; a.z += b.z; a.w += b.w;
}

// ---------------- fused setup: Wl transpose + edge count + embedding ----------------
// idx space = NN*HD (6.4M). Sub-ranges also do the transpose (98304) and count (NE).
__global__ void fused_setup_kernel(const float* __restrict__ Wl, float* __restrict__ wcatT,
                                   const int* __restrict__ dst, int* __restrict__ cnt,
                                   const int* __restrict__ text_idx,
                                   const float* __restrict__ emb, float* __restrict__ h) {
    int idx = blockIdx.x * blockDim.x + threadIdx.x;
    if (idx < 2 * 3 * 128 * 128) {
        int o  = idx & 127;
        int hh = (idx >> 7) & 127;
        int lt = idx >> 14;
        int t  = lt % 3;
        int l  = lt / 3;
        wcatT[(size_t)l * HD * K3 + (size_t)o * K3 + t * 128 + hh] = Wl[idx];
    }
    if (idx < NE) atomicAdd(&cnt[dst[idx]], 1);
    if (idx < NN * HD) {
        int n = idx >> 7, c = idx & 127;
        h[idx] = emb[(size_t)text_idx[n] * HD + c];
    }
}

// single-block scan with carry -> rowptr (exclusive, +1 shifted) and cursor
__global__ void scan_counts_kernel(const int* __restrict__ cnt, int* __restrict__ rowptr,
                                   int* __restrict__ cursor, int n) {
    __shared__ int sh[1024];
    __shared__ int carry;
    int tid = threadIdx.x;
    if (tid == 0) { carry = 0; rowptr[0] = 0; }
    __syncthreads();
    for (int base = 0; base < n; base += 1024) {
        int i = base + tid;
        int v = (i < n) ? cnt[i] : 0;
        sh[tid] = v;
        __syncthreads();
        for (int off = 1; off < 1024; off <<= 1) {
            int t = (tid >= off) ? sh[tid - off] : 0;
            __syncthreads();
            sh[tid] += t;
            __syncthreads();
        }
        int incl = sh[tid];
        int c = carry;
        if (i < n) {
            rowptr[i + 1] = c + incl;
            cursor[i]     = c + incl - v;
        }
        __syncthreads();
        if (tid == 1023) carry = c + sh[1023];
        __syncthreads();
    }
}

__global__ void place_edges_kernel(const int* __restrict__ src, const int* __restrict__ dst,
                                   const int* __restrict__ etype, int* __restrict__ cursor,
                                   int* __restrict__ edges) {
    int e = blockIdx.x * blockDim.x + threadIdx.x;
    if (e >= NE) return;
    int d = dst[e];
    int pos = atomicAdd(&cursor[d], 1);
    edges[pos] = src[e] | (etype[e] << 24);
}

__global__ void goff_kernel(const int* __restrict__ graph_id, int* __restrict__ goff) {
    int g = threadIdx.x;
    if (g > NG) return;
    if (g == NG) { goff[NG] = NN; return; }
    int lo = 0, hi = NN;
    while (lo < hi) {
        int mid = (lo + hi) >> 1;
        if (graph_id[mid] < g) lo = mid + 1; else hi = mid;
    }
    goff[g] = lo;
}

// segment mean of current h
__global__ void mean_kernel(const float* __restrict__ h, const int* __restrict__ goff,
                            float* __restrict__ agg, int slot) {
    int g = blockIdx.x;
    int c = threadIdx.x; // 128
    int s = goff[g], e = goff[g + 1];
    float a0 = 0.f, a1 = 0.f, a2 = 0.f, a3 = 0.f;
    int r = s;
    for (; r + 4 <= e; r += 4) {
        a0 += h[(size_t)(r + 0) * HD + c];
        a1 += h[(size_t)(r + 1) * HD + c];
        a2 += h[(size_t)(r + 2) * HD + c];
        a3 += h[(size_t)(r + 3) * HD + c];
    }
    for (; r < e; ++r) a0 += h[(size_t)r * HD + c];
    float acc = (a0 + a1) + (a2 + a3);
    float cntf = (float)((e - s) > 0 ? (e - s) : 1);
    agg[g * K3 + slot * HD + c] = acc / cntf;
}

// segment mean of the INITIAL embedding (slot 0) — recomputed from emb[text_idx],
// so it can run anytime after goff (h may already be updated).
__global__ void mean0_emb_kernel(const int* __restrict__ text_idx,
                                 const float* __restrict__ emb,
                                 const int* __restrict__ goff,
                                 float* __restrict__ agg) {
    int g = blockIdx.x;
    int c = threadIdx.x; // 128
    int s = goff[g], e = goff[g + 1];
    float a0 = 0.f, a1 = 0.f, a2 = 0.f, a3 = 0.f;
    int r = s;
    for (; r + 4 <= e; r += 4) {
        a0 += emb[(size_t)text_idx[r + 0] * HD + c];
        a1 += emb[(size_t)text_idx[r + 1] * HD + c];
        a2 += emb[(size_t)text_idx[r + 2] * HD + c];
        a3 += emb[(size_t)text_idx[r + 3] * HD + c];
    }
    for (; r < e; ++r) a0 += emb[(size_t)text_idx[r] * HD + c];
    float acc = (a0 + a1) + (a2 + a3);
    float cntf = (float)((e - s) > 0 ? (e - s) : 1);
    agg[g * K3 + c] = acc / cntf;
}

// one warp per dst node: per-etype raw-feature sums -> S[n][t*128 + col], deg counts
__global__ void aggregate_kernel(const float* __restrict__ h, const int* __restrict__ rowptr,
                                 const int* __restrict__ edges, float* __restrict__ S,
                                 float* __restrict__ deg) {
    int warp = (blockIdx.x * blockDim.x + threadIdx.x) >> 5;
    int lane = threadIdx.x & 31;
    if (warp >= NN) return;
    int s = rowptr[warp], e = rowptr[warp + 1];
    float4 a0 = {0,0,0,0}, a1 = {0,0,0,0}, a2 = {0,0,0,0};
    int c0 = 0, c1 = 0, c2 = 0;
    const float4* h4 = (const float4*)h;
    for (int i = s; i < e; ++i) {
        int p = edges[i];
        int srcn = p & 0xFFFFFF;
        int t = p >> 24;
        float4 v = h4[(size_t)srcn * 32 + lane];
        if (t == 0)      { f4add(a0, v); c0++; }
        else if (t == 1) { f4add(a1, v); c1++; }
        else             { f4add(a2, v); c2++; }
    }
    float4* S4 = (float4*)S;
    size_t base = (size_t)warp * 96;
    S4[base + lane]      = a0;
    S4[base + 32 + lane] = a1;
    S4[base + 64 + lane] = a2;
    if (lane == 0) {
        deg[(size_t)warp * 3 + 0] = (float)c0;
        deg[(size_t)warp * 3 + 1] = (float)c1;
        deg[(size_t)warp * 3 + 2] = (float)c2;
    }
}

// ---------------- TF32 tensor-core GEMM core: C_tile = A·B^T (+epilogue) ----------------
// A: [M x K] row-major (K mult of 32), B: pre-offset chunk [128 x K] row-major.
// Writes C[m][j0 + c] with row stride Jstride. bias/bl3 indexed by LOCAL col (0..127).
// mode 1: +bias[c]; mode 2: +deg[m][t]*bl3[t*128 + c]
// Block tile 128x128, BK=32, 256 threads = 8 warps, warp tile 64x32.
#define GEMM_SMEM_BYTES (2 * 128 * 36 * 2 * 4)

__device__ __forceinline__ void gemm_core(
    const float* __restrict__ A, const float* __restrict__ B, float* __restrict__ C,
    unsigned* sm, int M, int K, int Jstride, int m0, int j0, int mode,
    const float* __restrict__ bias, const float* __restrict__ deg,
    const float* __restrict__ bl3)
{
    unsigned* AsBase = sm;              // 2 x 128 x 36
    unsigned* BsBase = sm + 2 * 128 * 36;

    const int tid  = threadIdx.x;
    const int warp = tid >> 5;
    const int lane = tid & 31;
    const int g    = lane >> 2;   // 0..7
    const int tg   = lane & 3;    // 0..3
    const int wm   = (warp >> 2) * 64;   // 0 / 64
    const int wn   = (warp & 3) * 32;    // 0..96

    float acc[4][4][4];
#pragma unroll
    for (int mi = 0; mi < 4; ++mi)
#pragma unroll
        for (int ni = 0; ni < 4; ++ni)
#pragma unroll
            for (int q = 0; q < 4; ++q) acc[mi][ni][q] = 0.f;

    float4 rA[4], rB[4];
    const int numT = K >> 5;

    auto GLOAD = [&](int t) {
        int k0 = t << 5;
#pragma unroll
        for (int u = 0; u < 4; ++u) {
            int f  = tid + u * 256;
            int r  = f >> 3;
            int kq = (f & 7) << 2;
            int gm = m0 + r;
            rA[u] = (gm < M) ? *(const float4*)(A + (size_t)gm * K + k0 + kq)
                             : make_float4(0.f, 0.f, 0.f, 0.f);
            rB[u] = *(const float4*)(B + (size_t)r * K + k0 + kq);
        }
    };
    auto SSTORE = [&](int buf) {
        unsigned* a = AsBase + buf * (128 * 36);
        unsigned* b = BsBase + buf * (128 * 36);
#pragma unroll
        for (int u = 0; u < 4; ++u) {
            int f  = tid + u * 256;
            int r  = f >> 3;
            int kq = (f & 7) << 2;
            a[r * 36 + kq + 0] = cvt_tf32(rA[u].x);
            a[r * 36 + kq + 1] = cvt_tf32(rA[u].y);
            a[r * 36 + kq + 2] = cvt_tf32(rA[u].z);
            a[r * 36 + kq + 3] = cvt_tf32(rA[u].w);
            b[r * 36 + kq + 0] = cvt_tf32(rB[u].x);
            b[r * 36 + kq + 1] = cvt_tf32(rB[u].y);
            b[r * 36 + kq + 2] = cvt_tf32(rB[u].z);
            b[r * 36 + kq + 3] = cvt_tf32(rB[u].w);
        }
    };
    auto COMP = [&](int buf) {
        const unsigned* a = AsBase + buf * (128 * 36);
        const unsigned* b = BsBase + buf * (128 * 36);
#pragma unroll
        for (int kk = 0; kk < 32; kk += 8) {
            unsigned af[4][4], bf[4][2];
#pragma unroll
            for (int mi = 0; mi < 4; ++mi) {
                int r = wm + mi * 16 + g;
                af[mi][0] = a[r * 36 + kk + tg];
                af[mi][1] = a[(r + 8) * 36 + kk + tg];
                af[mi][2] = a[r * 36 + kk + tg + 4];
                af[mi][3] = a[(r + 8) * 36 + kk + tg + 4];
            }
#pragma unroll
            for (int ni = 0; ni < 4; ++ni) {
                int c = wn + ni * 8 + g;
                bf[ni][0] = b[c * 36 + kk + tg];
                bf[ni][1] = b[c * 36 + kk + tg + 4];
            }
#pragma unroll
            for (int mi = 0; mi < 4; ++mi)
#pragma unroll
                for (int ni = 0; ni < 4; ++ni) {
                    asm volatile(
                        "mma.sync.aligned.m16n8k8.row.col.f32.tf32.tf32.f32 "
                        "{%0,%1,%2,%3}, {%4,%5,%6,%7}, {%8,%9}, {%0,%1,%2,%3};"
                        : "+f"(acc[mi][ni][0]), "+f"(acc[mi][ni][1]),
                          "+f"(acc[mi][ni][2]), "+f"(acc[mi][ni][3])
                        : "r"(af[mi][0]), "r"(af[mi][1]), "r"(af[mi][2]), "r"(af[mi][3]),
                          "r"(bf[ni][0]), "r"(bf[ni][1]));
                }
        }
    };

    GLOAD(0); SSTORE(0); __syncthreads();
    for (int t = 0; t < numT; ++t) {
        if (t + 1 < numT) GLOAD(t + 1);
        COMP(t & 1);
        if (t + 1 < numT) SSTORE((t + 1) & 1);
        __syncthreads();
    }

    // epilogue
#pragma unroll
    for (int mi = 0; mi < 4; ++mi) {
        int r0 = m0 + wm + mi * 16 + g;
        int r1 = r0 + 8;
        float d00 = 0.f, d01 = 0.f, d02 = 0.f, d10 = 0.f, d11 = 0.f, d12 = 0.f;
        if (mode == 2) {
            if (r0 < M) { d00 = deg[(size_t)r0 * 3]; d01 = deg[(size_t)r0 * 3 + 1]; d02 = deg[(size_t)r0 * 3 + 2]; }
            if (r1 < M) { d10 = deg[(size_t)r1 * 3]; d11 = deg[(size_t)r1 * 3 + 1]; d12 = deg[(size_t)r1 * 3 + 2]; }
        }
#pragma unroll
        for (int ni = 0; ni < 4; ++ni) {
            int cl = wn + ni * 8 + tg * 2;    // local col 0..127
            float v00 = acc[mi][ni][0], v01 = acc[mi][ni][1];
            float v10 = acc[mi][ni][2], v11 = acc[mi][ni][3];
            if (mode == 1) {
                float bb0 = bias[cl], bb1 = bias[cl + 1];
                v00 += bb0; v01 += bb1; v10 += bb0; v11 += bb1;
            } else if (mode == 2) {
                float e00 = bl3[cl],       e01 = bl3[cl + 1];
                float e10 = bl3[128 + cl], e11 = bl3[129 + cl];
                float e20 = bl3[256 + cl], e21 = bl3[257 + cl];
                v00 += d00 * e00 + d01 * e10 + d02 * e20;
                v01 += d00 * e01 + d01 * e11 + d02 * e21;
                v10 += d10 * e00 + d11 * e10 + d12 * e20;
                v11 += d10 * e01 + d11 * e11 + d12 * e21;
            }
            if (r0 < M) *(float2*)(C + (size_t)r0 * Jstride + j0 + cl) = make_float2(v00, v01);
            if (r1 < M) *(float2*)(C + (size_t)r1 * Jstride + j0 + cl) = make_float2(v10, v11);
        }
    }
}

// GEMM1: a = S @ WcatT^T + deg-weighted etype bias  (K=384, J=128)
__global__ __launch_bounds__(256) void gemm1_kernel(
    const float* __restrict__ S, const float* __restrict__ wcatT_l, float* __restrict__ a,
    const float* __restrict__ deg, const float* __restrict__ bl3)
{
    extern __shared__ unsigned sm[];
    gemm_core(S, wcatT_l, a, sm, NN, K3, HD, blockIdx.x * 128, 0, 2, nullptr, deg, bl3);
}

// merged GEMM2+GEMM3: y<3 -> gi chunk y (A=a, B=W_ih), y>=3 -> gh chunk y-3 (A=h, B=W_hh)
__global__ __launch_bounds__(256) void gemm23_kernel(
    const float* __restrict__ a, const float* __restrict__ h,
    const float* __restrict__ W_ih_l, const float* __restrict__ W_hh_l,
    const float* __restrict__ b_ih_l, const float* __restrict__ b_hh_l,
    float* __restrict__ gi, float* __restrict__ gh)
{
    extern __shared__ unsigned sm[];
    int yb = blockIdx.y;
    int sel = (yb >= 3);
    int chunk = yb - 3 * sel;
    const float* A    = sel ? h : a;
    const float* B    = (sel ? W_hh_l : W_ih_l) + (size_t)chunk * 128 * HD;
    const float* bias = (sel ? b_hh_l : b_ih_l) + chunk * 128;
    float* C          = sel ? gh : gi;
    gemm_core(A, B, C, sm, NN, HD, K3, blockIdx.x * 128, chunk * 128, 1, bias, nullptr, nullptr);
}

// ---------------- GRU gates (in-place h update) ----------------
__global__ void gru_gates_kernel(const float* __restrict__ gi, const float* __restrict__ gh,
                                 float* __restrict__ h) {
    int idx = blockIdx.x * blockDim.x + threadIdx.x;
    if (idx >= NN * HD) return;
    int n = idx >> 7, c = idx & 127;
    size_t b = (size_t)n * K3;
    float ir = gi[b + c],       hr = gh[b + c];
    float iz = gi[b + 128 + c], hz = gh[b + 128 + c];
    float in_ = gi[b + 256 + c], hn = gh[b + 256 + c];
    float r = 1.f / (1.f + expf(-(ir + hr)));
    float z = 1.f / (1.f + expf(-(iz + hz)));
    float nc = tanhf(in_ + r * hn);
    h[idx] = (1.f - z) * nc + z * h[idx];
}

// ---------------- head: x = relu(agg@W1+b1); res = x@W2+b2; emit [res | agg] ------------
__global__ void head_kernel(const float* __restrict__ agg, const float* __restrict__ W1,
                            const float* __restrict__ b1, const float* __restrict__ W2,
                            const float* __restrict__ b2, float* __restrict__ out,
                            int out_size) {
    int g = blockIdx.x;
    int o = threadIdx.x; // 128
    __shared__ float sa[K3];
    __shared__ float sx[HD];
    for (int k = o; k < K3; k += HD) sa[k] = agg[g * K3 + k];
    __syncthreads();
    float acc = b1[o];
    for (int k = 0; k < K3; ++k) acc += sa[k] * W1[k * HD + o];
    acc = fmaxf(acc, 0.f);
    sx[o] = acc * W2[o];
    __syncthreads();
    for (int st = 64; st > 0; st >>= 1) {
        if (o < st) sx[o] += sx[o + st];
        __syncthreads();
    }
    if (o == 0 && g < out_size) out[g] = sx[0] + b2[0];
    for (int k = o; k < K3; k += HD) {
        int oi = NG + g * K3 + k;
        if (oi < out_size) out[oi] = sa[k];
    }
}

// ---------------- host launch ----------------
extern "C" void kernel_launch(void* const* d_in, const int* in_sizes, int n_in,
                              void* d_out, int out_size) {
    const int*   text_idx = (const int*)d_in[0];
    const int*   src      = (const int*)d_in[1];
    const int*   dst      = (const int*)d_in[2];
    const int*   etype    = (const int*)d_in[3];
    const int*   graph_id = (const int*)d_in[4];
    const float* emb      = (const float*)d_in[5];
    const float* Wl       = (const float*)d_in[6];
    const float* bl       = (const float*)d_in[7];
    const float* W_ih     = (const float*)d_in[8];
    const float* W_hh     = (const float*)d_in[9];
    const float* b_ih     = (const float*)d_in[10];
    const float* b_hh     = (const float*)d_in[11];
    const float* W1       = (const float*)d_in[12];
    const float* b1       = (const float*)d_in[13];
    const float* W2       = (const float*)d_in[14];
    const float* b2       = (const float*)d_in[15];
    float* out = (float*)d_out;

    float *h, *S, *a, *gi, *gh, *deg, *wcatT, *agg;
    int *cnt, *rowptr, *cursor, *edges, *goff;
    cudaGetSymbolAddress((void**)&h,      d_h);
    cudaGetSymbolAddress((void**)&S,      d_S);
    cudaGetSymbolAddress((void**)&a,      d_a);
    cudaGetSymbolAddress((void**)&gi,     d_gi);
    cudaGetSymbolAddress((void**)&gh,     d_gh);
    cudaGetSymbolAddress((void**)&deg,    d_deg);
    cudaGetSymbolAddress((void**)&wcatT,  d_wcatT);
    cudaGetSymbolAddress((void**)&agg,    d_agg);
    cudaGetSymbolAddress((void**)&cnt,    d_cnt);
    cudaGetSymbolAddress((void**)&rowptr, d_rowptr);
    cudaGetSymbolAddress((void**)&cursor, d_cursor);
    cudaGetSymbolAddress((void**)&edges,  d_edges);
    cudaGetSymbolAddress((void**)&goff,   d_goff);

    static bool attr_set = false;
    if (!attr_set) {
        cudaFuncSetAttribute(gemm1_kernel,
                             cudaFuncAttributeMaxDynamicSharedMemorySize, GEMM_SMEM_BYTES);
        cudaFuncSetAttribute(gemm23_kernel,
                             cudaFuncAttributeMaxDynamicSharedMemorySize, GEMM_SMEM_BYTES);
        attr_set = true;
    }

    // ---- setup (ordered so launch slot ~5 is aggregate_kernel for ncu) ----
    cudaMemsetAsync(cnt, 0, NN * sizeof(int));
    fused_setup_kernel<<<(NN * HD + 255) / 256, 256>>>(Wl, wcatT, dst, cnt, text_idx, emb, h);
    scan_counts_kernel<<<1, 1024>>>(cnt, rowptr, cursor, NN);
    place_edges_kernel<<<(NE + 255) / 256, 256>>>(src, dst, etype, cursor, edges);

    const dim3 g1((NN + 127) / 128, 1);
    const dim3 g23((NN + 127) / 128, 6);
    bool goff_done = false;

    for (int l = 0; l < NLAYERS; ++l) {
        for (int s = 0; s < NSTEPS; ++s) {
            aggregate_kernel<<<(NN * 32 + 255) / 256, 256>>>(h, rowptr, edges, S, deg);
            gemm1_kernel<<<g1, 256, GEMM_SMEM_BYTES>>>(
                S, wcatT + (size_t)l * HD * K3, a, deg, bl + l * K3);
            gemm23_kernel<<<g23, 256, GEMM_SMEM_BYTES>>>(
                a, h,
                W_ih + (size_t)l * K3 * HD, W_hh + (size_t)l * K3 * HD,
                b_ih + l * K3, b_hh + l * K3, gi, gh);
            gru_gates_kernel<<<(NN * HD + 255) / 256, 256>>>(gi, gh, h);
            if (!goff_done) {
                goff_kernel<<<1, NG + 1>>>(graph_id, goff);
                goff_done = true;
            }
        }
        mean_kernel<<<NG, HD>>>(h, goff, agg, l + 1);
    }

    mean0_emb_kernel<<<NG, HD>>>(text_idx, emb, goff, agg);
    head_kernel<<<NG, HD>>>(agg, W1, b1, W2, b2, out, out_size);
}

// round 8
// speedup vs baseline: 1.1482x; 1.0653x over previous
#include <cuda_runtime.h>
#include <math.h>
#include <stdint.h>

// ---------------- problem constants ----------------
#define NN 50000         // nodes
#define NE 600000        // edges
#define HD 128           // hidden
#define NG 64            // graphs
#define K3 384           // 3*H
#define NLAYERS 2
#define NSTEPS 2

// ---------------- device scratch (no allocs allowed) ----------------
__device__ float d_h[(size_t)NN * HD];
__device__ float d_S[(size_t)NN * K3];
__device__ float d_a[(size_t)NN * HD];
__device__ float d_gi[(size_t)NN * K3];   // planes: r | z | i_n
__device__ float d_gh[(size_t)NN * K3];   // plane:  h_n (first third used)
__device__ float d_deg[(size_t)NN * 3];
__device__ int   d_cnt[NN];
__device__ int   d_rowptr[NN + 1];
__device__ int   d_cursor[NN];
__device__ int   d_edges[NE];
__device__ int   d_goff[NG + 1];
__device__ float d_wcatT[2 * HD * K3];   // per layer: [128 out][384 k]
__device__ float d_agg[NG * K3];

__device__ __forceinline__ unsigned cvt_tf32(float x) {
    unsigned r;
    asm("cvt.rna.tf32.f32 %0, %1;" : "=r"(r) : "f"(x));
    return r;
}

__device__ __forceinline__ void f4add(float4& a, const float4& b) {
    a.x += b.x; a.y += b.y; a.z += b.z; a.w += b.w;
}

// ---------------- small kernels (R4-identical) ----------------

__global__ void transpose_wl_kernel(const float* __restrict__ Wl, float* __restrict__ wcatT) {
    int idx = blockIdx.x * blockDim.x + threadIdx.x;
    if (idx >= 2 * 3 * 128 * 128) return;
    int o  = idx & 127;
    int hh = (idx >> 7) & 127;
    int lt = idx >> 14;
    int t  = lt % 3;
    int l  = lt / 3;
    wcatT[(size_t)l * HD * K3 + (size_t)o * K3 + t * 128 + hh] = Wl[idx];
}

__global__ void count_edges_kernel(const int* __restrict__ dst, int* __restrict__ cnt) {
    int e = blockIdx.x * blockDim.x + threadIdx.x;
    if (e < NE) atomicAdd(&cnt[dst[e]], 1);
}

__global__ void scan_counts_kernel(const int* __restrict__ cnt, int* __restrict__ rowptr,
                                   int* __restrict__ cursor, int n) {
    __shared__ int sh[1024];
    __shared__ int carry;
    int tid = threadIdx.x;
    if (tid == 0) { carry = 0; rowptr[0] = 0; }
    __syncthreads();
    for (int base = 0; base < n; base += 1024) {
        int i = base + tid;
        int v = (i < n) ? cnt[i] : 0;
        sh[tid] = v;
        __syncthreads();
        for (int off = 1; off < 1024; off <<= 1) {
            int t = (tid >= off) ? sh[tid - off] : 0;
            __syncthreads();
            sh[tid] += t;
            __syncthreads();
        }
        int incl = sh[tid];
        int c = carry;
        if (i < n) {
            rowptr[i + 1] = c + incl;
            cursor[i]     = c + incl - v;
        }
        __syncthreads();
        if (tid == 1023) carry = c + sh[1023];
        __syncthreads();
    }
}

__global__ void place_edges_kernel(const int* __restrict__ src, const int* __restrict__ dst,
                                   const int* __restrict__ etype, int* __restrict__ cursor,
                                   int* __restrict__ edges) {
    int e = blockIdx.x * blockDim.x + threadIdx.x;
    if (e >= NE) return;
    int d = dst[e];
    int pos = atomicAdd(&cursor[d], 1);
    edges[pos] = src[e] | (etype[e] << 24);
}

__global__ void goff_kernel(const int* __restrict__ graph_id, int* __restrict__ goff) {
    int g = threadIdx.x;
    if (g > NG) return;
    if (g == NG) { goff[NG] = NN; return; }
    int lo = 0, hi = NN;
    while (lo < hi) {
        int mid = (lo + hi) >> 1;
        if (graph_id[mid] < g) lo = mid + 1; else hi = mid;
    }
    goff[g] = lo;
}

__global__ void embed_kernel(const int* __restrict__ text_idx, const float* __restrict__ emb,
                             float* __restrict__ h) {
    int idx = blockIdx.x * blockDim.x + threadIdx.x;
    if (idx >= NN * HD) return;
    int n = idx >> 7, c = idx & 127;
    h[idx] = emb[(size_t)text_idx[n] * HD + c];
}

__global__ void mean_kernel(const float* __restrict__ h, const int* __restrict__ goff,
                            float* __restrict__ agg, int slot) {
    int g = blockIdx.x;
    int c = threadIdx.x; // 128
    int s = goff[g], e = goff[g + 1];
    float a0 = 0.f, a1 = 0.f, a2 = 0.f, a3 = 0.f;
    int r = s;
    for (; r + 4 <= e; r += 4) {
        a0 += h[(size_t)(r + 0) * HD + c];
        a1 += h[(size_t)(r + 1) * HD + c];
        a2 += h[(size_t)(r + 2) * HD + c];
        a3 += h[(size_t)(r + 3) * HD + c];
    }
    for (; r < e; ++r) a0 += h[(size_t)r * HD + c];
    float acc = (a0 + a1) + (a2 + a3);
    float cntf = (float)((e - s) > 0 ? (e - s) : 1);
    agg[g * K3 + slot * HD + c] = acc / cntf;
}

// one warp per dst node: per-etype raw-feature sums -> S[n][t*128 + col], deg counts
__global__ void aggregate_kernel(const float* __restrict__ h, const int* __restrict__ rowptr,
                                 const int* __restrict__ edges, float* __restrict__ S,
                                 float* __restrict__ deg) {
    int warp = (blockIdx.x * blockDim.x + threadIdx.x) >> 5;
    int lane = threadIdx.x & 31;
    if (warp >= NN) return;
    int s = rowptr[warp], e = rowptr[warp + 1];
    float4 a0 = {0,0,0,0}, a1 = {0,0,0,0}, a2 = {0,0,0,0};
    int c0 = 0, c1 = 0, c2 = 0;
    const float4* h4 = (const float4*)h;
    for (int i = s; i < e; ++i) {
        int p = edges[i];
        int srcn = p & 0xFFFFFF;
        int t = p >> 24;
        float4 v = h4[(size_t)srcn * 32 + lane];
        if (t == 0)      { f4add(a0, v); c0++; }
        else if (t == 1) { f4add(a1, v); c1++; }
        else             { f4add(a2, v); c2++; }
    }
    float4* S4 = (float4*)S;
    size_t base = (size_t)warp * 96;
    S4[base + lane]      = a0;
    S4[base + 32 + lane] = a1;
    S4[base + 64 + lane] = a2;
    if (lane == 0) {
        deg[(size_t)warp * 3 + 0] = (float)c0;
        deg[(size_t)warp * 3 + 1] = (float)c1;
        deg[(size_t)warp * 3 + 2] = (float)c2;
    }
}

// ---------------- TF32 GEMM (R4-identical): C[m][j] = sum_k A[m][k]*B[j][k] ----------------
#define GEMM_SMEM_BYTES (2 * 128 * 36 * 2 * 4)

__global__ __launch_bounds__(256) void tf32gemm_abt_kernel(
    const float* __restrict__ A, const float* __restrict__ B, float* __restrict__ C,
    int M, int K, int J, int mode,
    const float* __restrict__ bias, const float* __restrict__ deg,
    const float* __restrict__ bl3)
{
    extern __shared__ unsigned sm[];
    unsigned* AsBase = sm;
    unsigned* BsBase = sm + 2 * 128 * 36;

    const int tid = threadIdx.x;
    const int warp = tid >> 5;
    const int lane = tid & 31;
    const int g    = lane >> 2;
    const int tg   = lane & 3;
    const int wm   = (warp >> 2) * 64;
    const int wn   = (warp & 3) * 32;
    const int m0   = blockIdx.x * 128;
    const int j0   = blockIdx.y * 128;

    float acc[4][4][4];
#pragma unroll
    for (int mi = 0; mi < 4; ++mi)
#pragma unroll
        for (int ni = 0; ni < 4; ++ni)
#pragma unroll
            for (int q = 0; q < 4; ++q) acc[mi][ni][q] = 0.f;

    float4 rA[4], rB[4];
    const int numT = K >> 5;

    auto GLOAD = [&](int t) {
        int k0 = t << 5;
#pragma unroll
        for (int u = 0; u < 4; ++u) {
            int f  = tid + u * 256;
            int r  = f >> 3;
            int kq = (f & 7) << 2;
            int gm = m0 + r;
            rA[u] = (gm < M) ? *(const float4*)(A + (size_t)gm * K + k0 + kq)
                             : make_float4(0.f, 0.f, 0.f, 0.f);
            rB[u] = *(const float4*)(B + (size_t)(j0 + r) * K + k0 + kq);
        }
    };
    auto SSTORE = [&](int buf) {
        unsigned* a = AsBase + buf * (128 * 36);
        unsigned* b = BsBase + buf * (128 * 36);
#pragma unroll
        for (int u = 0; u < 4; ++u) {
            int f  = tid + u * 256;
            int r  = f >> 3;
            int kq = (f & 7) << 2;
            a[r * 36 + kq + 0] = cvt_tf32(rA[u].x);
            a[r * 36 + kq + 1] = cvt_tf32(rA[u].y);
            a[r * 36 + kq + 2] = cvt_tf32(rA[u].z);
            a[r * 36 + kq + 3] = cvt_tf32(rA[u].w);
            b[r * 36 + kq + 0] = cvt_tf32(rB[u].x);
            b[r * 36 + kq + 1] = cvt_tf32(rB[u].y);
            b[r * 36 + kq + 2] = cvt_tf32(rB[u].z);
            b[r * 36 + kq + 3] = cvt_tf32(rB[u].w);
        }
    };
    auto COMP = [&](int buf) {
        const unsigned* a = AsBase + buf * (128 * 36);
        const unsigned* b = BsBase + buf * (128 * 36);
#pragma unroll
        for (int kk = 0; kk < 32; kk += 8) {
            unsigned af[4][4], bf[4][2];
#pragma unroll
            for (int mi = 0; mi < 4; ++mi) {
                int r = wm + mi * 16 + g;
                af[mi][0] = a[r * 36 + kk + tg];
                af[mi][1] = a[(r + 8) * 36 + kk + tg];
                af[mi][2] = a[r * 36 + kk + tg + 4];
                af[mi][3] = a[(r + 8) * 36 + kk + tg + 4];
            }
#pragma unroll
            for (int ni = 0; ni < 4; ++ni) {
                int c = wn + ni * 8 + g;
                bf[ni][0] = b[c * 36 + kk + tg];
                bf[ni][1] = b[c * 36 + kk + tg + 4];
            }
#pragma unroll
            for (int mi = 0; mi < 4; ++mi)
#pragma unroll
                for (int ni = 0; ni < 4; ++ni) {
                    asm volatile(
                        "mma.sync.aligned.m16n8k8.row.col.f32.tf32.tf32.f32 "
                        "{%0,%1,%2,%3}, {%4,%5,%6,%7}, {%8,%9}, {%0,%1,%2,%3};"
                        : "+f"(acc[mi][ni][0]), "+f"(acc[mi][ni][1]),
                          "+f"(acc[mi][ni][2]), "+f"(acc[mi][ni][3])
                        : "r"(af[mi][0]), "r"(af[mi][1]), "r"(af[mi][2]), "r"(af[mi][3]),
                          "r"(bf[ni][0]), "r"(bf[ni][1]));
                }
        }
    };

    GLOAD(0); SSTORE(0); __syncthreads();
    for (int t = 0; t < numT; ++t) {
        if (t + 1 < numT) GLOAD(t + 1);
        COMP(t & 1);
        if (t + 1 < numT) SSTORE((t + 1) & 1);
        __syncthreads();
    }

#pragma unroll
    for (int mi = 0; mi < 4; ++mi) {
        int r0 = m0 + wm + mi * 16 + g;
        int r1 = r0 + 8;
        float d00 = 0.f, d01 = 0.f, d02 = 0.f, d10 = 0.f, d11 = 0.f, d12 = 0.f;
        if (mode == 2) {
            if (r0 < M) { d00 = deg[(size_t)r0 * 3]; d01 = deg[(size_t)r0 * 3 + 1]; d02 = deg[(size_t)r0 * 3 + 2]; }
            if (r1 < M) { d10 = deg[(size_t)r1 * 3]; d11 = deg[(size_t)r1 * 3 + 1]; d12 = deg[(size_t)r1 * 3 + 2]; }
        }
#pragma unroll
        for (int ni = 0; ni < 4; ++ni) {
            int cl = wn + ni * 8 + tg * 2;
            int c  = j0 + cl;
            float v00 = acc[mi][ni][0], v01 = acc[mi][ni][1];
            float v10 = acc[mi][ni][2], v11 = acc[mi][ni][3];
            if (mode == 1) {
                float bb0 = bias[c], bb1 = bias[c + 1];
                v00 += bb0; v01 += bb1; v10 += bb0; v11 += bb1;
            } else if (mode == 2) {
                float e00 = bl3[cl],       e01 = bl3[cl + 1];
                float e10 = bl3[128 + cl], e11 = bl3[129 + cl];
                float e20 = bl3[256 + cl], e21 = bl3[257 + cl];
                v00 += d00 * e00 + d01 * e10 + d02 * e20;
                v01 += d00 * e01 + d01 * e11 + d02 * e21;
                v10 += d10 * e00 + d11 * e10 + d12 * e20;
                v11 += d10 * e01 + d11 * e11 + d12 * e21;
            }
            if (r0 < M) *(float2*)(C + (size_t)r0 * J + c) = make_float2(v00, v01);
            if (r1 < M) *(float2*)(C + (size_t)r1 * J + c) = make_float2(v10, v11);
        }
    }
}

// ---------------- paired GEMM (gi-chunk + gh-chunk into one tile) + partial gates --------
// grid (391, 3): chunk 0 -> r = sigmoid(a@Wih_r^T + h@Whh_r^T + b); chunk 1 -> z likewise;
// chunk 2 -> i_n and h_n stored separately. Outputs are [NN x 128] planes.
__global__ __launch_bounds__(256) void gemm_pair_kernel(
    const float* __restrict__ abuf, const float* __restrict__ hbuf,
    const float* __restrict__ W_ih_l, const float* __restrict__ W_hh_l,
    const float* __restrict__ b_ih_l, const float* __restrict__ b_hh_l,
    float* __restrict__ rbuf, float* __restrict__ zbuf,
    float* __restrict__ inbuf, float* __restrict__ hnbuf)
{
    extern __shared__ unsigned sm[];
    unsigned* AsBase = sm;
    unsigned* BsBase = sm + 2 * 128 * 36;

    const int tid  = threadIdx.x;
    const int warp = tid >> 5;
    const int lane = tid & 31;
    const int g    = lane >> 2;
    const int tg   = lane & 3;
    const int wm   = (warp >> 2) * 64;
    const int wn   = (warp & 3) * 32;
    const int m0   = blockIdx.x * 128;
    const int chunk = blockIdx.y;

    float acc[4][4][4];
    float4 rA[4], rB[4];

    auto CLEAR = [&]() {
#pragma unroll
        for (int mi = 0; mi < 4; ++mi)
#pragma unroll
            for (int ni = 0; ni < 4; ++ni)
#pragma unroll
                for (int q = 0; q < 4; ++q) acc[mi][ni][q] = 0.f;
    };
    auto GLOAD = [&](const float* __restrict__ A, const float* __restrict__ B, int t) {
        int k0 = t << 5;
#pragma unroll
        for (int u = 0; u < 4; ++u) {
            int f  = tid + u * 256;
            int r  = f >> 3;
            int kq = (f & 7) << 2;
            int gm = m0 + r;
            rA[u] = (gm < NN) ? *(const float4*)(A + (size_t)gm * HD + k0 + kq)
                              : make_float4(0.f, 0.f, 0.f, 0.f);
            rB[u] = *(const float4*)(B + (size_t)r * HD + k0 + kq);
        }
    };
    auto SSTORE = [&](int buf) {
        unsigned* a = AsBase + buf * (128 * 36);
        unsigned* b = BsBase + buf * (128 * 36);
#pragma unroll
        for (int u = 0; u < 4; ++u) {
            int f  = tid + u * 256;
            int r  = f >> 3;
            int kq = (f & 7) << 2;
            a[r * 36 + kq + 0] = cvt_tf32(rA[u].x);
            a[r * 36 + kq + 1] = cvt_tf32(rA[u].y);
            a[r * 36 + kq + 2] = cvt_tf32(rA[u].z);
            a[r * 36 + kq + 3] = cvt_tf32(rA[u].w);
            b[r * 36 + kq + 0] = cvt_tf32(rB[u].x);
            b[r * 36 + kq + 1] = cvt_tf32(rB[u].y);
            b[r * 36 + kq + 2] = cvt_tf32(rB[u].z);
            b[r * 36 + kq + 3] = cvt_tf32(rB[u].w);
        }
    };
    auto COMP = [&](int buf) {
        const unsigned* a = AsBase + buf * (128 * 36);
        const unsigned* b = BsBase + buf * (128 * 36);
#pragma unroll
        for (int kk = 0; kk < 32; kk += 8) {
            unsigned af[4][4], bf[4][2];
#pragma unroll
            for (int mi = 0; mi < 4; ++mi) {
                int r = wm + mi * 16 + g;
                af[mi][0] = a[r * 36 + kk + tg];
                af[mi][1] = a[(r + 8) * 36 + kk + tg];
                af[mi][2] = a[r * 36 + kk + tg + 4];
                af[mi][3] = a[(r + 8) * 36 + kk + tg + 4];
            }
#pragma unroll
            for (int ni = 0; ni < 4; ++ni) {
                int c = wn + ni * 8 + g;
                bf[ni][0] = b[c * 36 + kk + tg];
                bf[ni][1] = b[c * 36 + kk + tg + 4];
            }
#pragma unroll
            for (int mi = 0; mi < 4; ++mi)
#pragma unroll
                for (int ni = 0; ni < 4; ++ni) {
                    asm volatile(
                        "mma.sync.aligned.m16n8k8.row.col.f32.tf32.tf32.f32 "
                        "{%0,%1,%2,%3}, {%4,%5,%6,%7}, {%8,%9}, {%0,%1,%2,%3};"
                        : "+f"(acc[mi][ni][0]), "+f"(acc[mi][ni][1]),
                          "+f"(acc[mi][ni][2]), "+f"(acc[mi][ni][3])
                        : "r"(af[mi][0]), "r"(af[mi][1]), "r"(af[mi][2]), "r"(af[mi][3]),
                          "r"(bf[ni][0]), "r"(bf[ni][1]));
                }
        }
    };
    auto RUN = [&](const float* __restrict__ A, const float* __restrict__ B) {
        GLOAD(A, B, 0); SSTORE(0); __syncthreads();
#pragma unroll
        for (int t = 0; t < 4; ++t) {
            if (t + 1 < 4) GLOAD(A, B, t + 1);
            COMP(t & 1);
            if (t + 1 < 4) SSTORE((t + 1) & 1);
            __syncthreads();
        }
    };
    // STORE_EPI: out[m][cl] = f(acc + bias0[cl] (+bias1[cl])); sig => sigmoid
    auto STORE_EPI = [&](float* __restrict__ out, const float* __restrict__ bias0,
                         const float* __restrict__ bias1, bool sig) {
#pragma unroll
        for (int mi = 0; mi < 4; ++mi) {
            int r0 = m0 + wm + mi * 16 + g;
            int r1 = r0 + 8;
#pragma unroll
            for (int ni = 0; ni < 4; ++ni) {
                int cl = wn + ni * 8 + tg * 2;
                float bb0 = bias0[cl], bb1 = bias0[cl + 1];
                if (bias1) { bb0 += bias1[cl]; bb1 += bias1[cl + 1]; }
                float v00 = acc[mi][ni][0] + bb0, v01 = acc[mi][ni][1] + bb1;
                float v10 = acc[mi][ni][2] + bb0, v11 = acc[mi][ni][3] + bb1;
                if (sig) {
                    v00 = 1.f / (1.f + expf(-v00));
                    v01 = 1.f / (1.f + expf(-v01));
                    v10 = 1.f / (1.f + expf(-v10));
                    v11 = 1.f / (1.f + expf(-v11));
                }
                if (r0 < NN) *(float2*)(out + (size_t)r0 * HD + cl) = make_float2(v00, v01);
                if (r1 < NN) *(float2*)(out + (size_t)r1 * HD + cl) = make_float2(v10, v11);
            }
        }
    };

    if (chunk < 2) {
        CLEAR();
        RUN(abuf, W_ih_l + (size_t)chunk * 128 * HD);
        RUN(hbuf, W_hh_l + (size_t)chunk * 128 * HD);
        STORE_EPI(chunk == 0 ? rbuf : zbuf,
                  b_ih_l + chunk * 128, b_hh_l + chunk * 128, true);
    } else {
        CLEAR();
        RUN(abuf, W_ih_l + (size_t)256 * HD);
        STORE_EPI(inbuf, b_ih_l + 256, nullptr, false);
        CLEAR();
        RUN(hbuf, W_hh_l + (size_t)256 * HD);
        STORE_EPI(hnbuf, b_hh_l + 256, nullptr, false);
    }
}

// ---------------- final gates: h = (1-z)*tanh(i_n + r*h_n) + z*h ----------------
__global__ void gates_kernel(const float* __restrict__ rbuf, const float* __restrict__ zbuf,
                             const float* __restrict__ inbuf, const float* __restrict__ hnbuf,
                             float* __restrict__ h) {
    int idx = blockIdx.x * blockDim.x + threadIdx.x;
    if (idx >= NN * HD) return;
    float r = rbuf[idx], z = zbuf[idx];
    float nc = tanhf(inbuf[idx] + r * hnbuf[idx]);
    h[idx] = (1.f - z) * nc + z * h[idx];
}

// ---------------- head ----------------
__global__ void head_kernel(const float* __restrict__ agg, const float* __restrict__ W1,
                            const float* __restrict__ b1, const float* __restrict__ W2,
                            const float* __restrict__ b2, float* __restrict__ out,
                            int out_size) {
    int g = blockIdx.x;
    int o = threadIdx.x; // 128
    __shared__ float sa[K3];
    __shared__ float sx[HD];
    for (int k = o; k < K3; k += HD) sa[k] = agg[g * K3 + k];
    __syncthreads();
    float acc = b1[o];
    for (int k = 0; k < K3; ++k) acc += sa[k] * W1[k * HD + o];
    acc = fmaxf(acc, 0.f);
    sx[o] = acc * W2[o];
    __syncthreads();
    for (int st = 64; st > 0; st >>= 1) {
        if (o < st) sx[o] += sx[o + st];
        __syncthreads();
    }
    if (o == 0 && g < out_size) out[g] = sx[0] + b2[0];
    for (int k = o; k < K3; k += HD) {
        int oi = NG + g * K3 + k;
        if (oi < out_size) out[oi] = sa[k];
    }
}

// ---------------- host launch (R4 ordering) ----------------
extern "C" void kernel_launch(void* const* d_in, const int* in_sizes, int n_in,
                              void* d_out, int out_size) {
    const int*   text_idx = (const int*)d_in[0];
    const int*   src      = (const int*)d_in[1];
    const int*   dst      = (const int*)d_in[2];
    const int*   etype    = (const int*)d_in[3];
    const int*   graph_id = (const int*)d_in[4];
    const float* emb      = (const float*)d_in[5];
    const float* Wl       = (const float*)d_in[6];
    const float* bl       = (const float*)d_in[7];
    const float* W_ih     = (const float*)d_in[8];
    const float* W_hh     = (const float*)d_in[9];
    const float* b_ih     = (const float*)d_in[10];
    const float* b_hh     = (const float*)d_in[11];
    const float* W1       = (const float*)d_in[12];
    const float* b1       = (const float*)d_in[13];
    const float* W2       = (const float*)d_in[14];
    const float* b2       = (const float*)d_in[15];
    float* out = (float*)d_out;

    float *h, *S, *a, *gi, *gh, *deg, *wcatT, *agg;
    int *cnt, *rowptr, *cursor, *edges, *goff;
    cudaGetSymbolAddress((void**)&h,      d_h);
    cudaGetSymbolAddress((void**)&S,      d_S);
    cudaGetSymbolAddress((void**)&a,      d_a);
    cudaGetSymbolAddress((void**)&gi,     d_gi);
    cudaGetSymbolAddress((void**)&gh,     d_gh);
    cudaGetSymbolAddress((void**)&deg,    d_deg);
    cudaGetSymbolAddress((void**)&wcatT,  d_wcatT);
    cudaGetSymbolAddress((void**)&agg,    d_agg);
    cudaGetSymbolAddress((void**)&cnt,    d_cnt);
    cudaGetSymbolAddress((void**)&rowptr, d_rowptr);
    cudaGetSymbolAddress((void**)&cursor, d_cursor);
    cudaGetSymbolAddress((void**)&edges,  d_edges);
    cudaGetSymbolAddress((void**)&goff,   d_goff);

    // gate planes (reuse gi/gh scratch)
    float* rbuf  = gi;
    float* zbuf  = gi + (size_t)NN * HD;
    float* inbuf = gi + (size_t)2 * NN * HD;
    float* hnbuf = gh;

    static bool attr_set = false;
    if (!attr_set) {
        cudaFuncSetAttribute(tf32gemm_abt_kernel,
                             cudaFuncAttributeMaxDynamicSharedMemorySize, GEMM_SMEM_BYTES);
        cudaFuncSetAttribute(gemm_pair_kernel,
                             cudaFuncAttributeMaxDynamicSharedMemorySize, GEMM_SMEM_BYTES);
        attr_set = true;
    }

    // ---- setup (R4 order) ----
    transpose_wl_kernel<<<(2 * 3 * 128 * 128 + 255) / 256, 256>>>(Wl, wcatT);
    cudaMemsetAsync(cnt, 0, NN * sizeof(int));
    count_edges_kernel<<<(NE + 255) / 256, 256>>>(dst, cnt);
    scan_counts_kernel<<<1, 1024>>>(cnt, rowptr, cursor, NN);
    place_edges_kernel<<<(NE + 255) / 256, 256>>>(src, dst, etype, cursor, edges);
    goff_kernel<<<1, NG + 1>>>(graph_id, goff);

    embed_kernel<<<(NN * HD + 255) / 256, 256>>>(text_idx, emb, h);
    mean_kernel<<<NG, HD>>>(h, goff, agg, 0);

    const dim3 g1((NN + 127) / 128, 1);
    const dim3 gp((NN + 127) / 128, 3);

    for (int l = 0; l < NLAYERS; ++l) {
        for (int s = 0; s < NSTEPS; ++s) {
            aggregate_kernel<<<(NN * 32 + 255) / 256, 256>>>(h, rowptr, edges, S, deg);
            // a = S @ WcatT^T + deg-weighted etype bias
            tf32gemm_abt_kernel<<<g1, 256, GEMM_SMEM_BYTES>>>(
                S, wcatT + (size_t)l * HD * K3, a,
                NN, K3, HD, 2, nullptr, deg, bl + l * K3);
            // paired gi/gh GEMMs with partial gate fusion
            gemm_pair_kernel<<<gp, 256, GEMM_SMEM_BYTES>>>(
                a, h,
                W_ih + (size_t)l * K3 * HD, W_hh + (size_t)l * K3 * HD,
                b_ih + l * K3, b_hh + l * K3,
                rbuf, zbuf, inbuf, hnbuf);
            gates_kernel<<<(NN * HD + 255) / 256, 256>>>(rbuf, zbuf, inbuf, hnbuf, h);
        }
        mean_kernel<<<NG, HD>>>(h, goff, agg, l + 1);
    }

    head_kernel<<<NG, HD>>>(agg, W1, b1, W2, b2, out, out_size);
}

// round 9
// speedup vs baseline: 1.1802x; 1.0279x over previous
#include <cuda_runtime.h>
#include <math.h>
#include <stdint.h>

// ---------------- problem constants ----------------
#define NN 50000         // nodes
#define NE 600000        // edges
#define HD 128           // hidden
#define NG 64            // graphs
#define K3 384           // 3*H
#define NLAYERS 2
#define NSTEPS 2

// ---------------- device scratch (no allocs allowed) ----------------
__device__ float d_h[(size_t)NN * HD];
__device__ float d_S[(size_t)NN * K3];
__device__ float d_a[(size_t)NN * HD];
__device__ float d_gi[(size_t)NN * K3];   // planes: r | z | i_n
__device__ float d_gh[(size_t)NN * K3];   // planes: h_n | h32 (rounded h copy)
__device__ float d_deg[(size_t)NN * 3];
__device__ int   d_cnt[NN];
__device__ int   d_rowptr[NN + 1];
__device__ int   d_cursor[NN];
__device__ int   d_edges[NE];
__device__ int   d_goff[NG + 1];
__device__ float d_wcatT[2 * HD * K3];   // per layer: [128 out][384 k], tf32-rounded
__device__ float d_wih32[2 * K3 * HD];   // tf32-rounded W_ih
__device__ float d_whh32[2 * K3 * HD];   // tf32-rounded W_hh
__device__ float d_agg[NG * K3];

__device__ __forceinline__ unsigned cvt_tf32(float x) {
    unsigned r;
    asm("cvt.rna.tf32.f32 %0, %1;" : "=r"(r) : "f"(x));
    return r;
}
__device__ __forceinline__ float rnd_tf32(float x) {
    return __uint_as_float(cvt_tf32(x));
}

__device__ __forceinline__ void f4add(float4& a, const float4& b) {
    a.x += b.x; a.y += b.y; a.z += b.z; a.w += b.w;
}

// ---------------- small setup kernels ----------------

// WcatT[l][o][t*128+h] = round(Wl[l][t][h][o])
__global__ void transpose_wl_kernel(const float* __restrict__ Wl, float* __restrict__ wcatT) {
    int idx = blockIdx.x * blockDim.x + threadIdx.x;
    if (idx >= 2 * 3 * 128 * 128) return;
    int o  = idx & 127;
    int hh = (idx >> 7) & 127;
    int lt = idx >> 14;
    int t  = lt % 3;
    int l  = lt / 3;
    wcatT[(size_t)l * HD * K3 + (size_t)o * K3 + t * 128 + hh] = rnd_tf32(Wl[idx]);
}

// rounded copies of GRU weights
__global__ void round_w_kernel(const float* __restrict__ Wih, const float* __restrict__ Whh,
                               float* __restrict__ wih32, float* __restrict__ whh32) {
    int idx = blockIdx.x * blockDim.x + threadIdx.x;
    if (idx >= 2 * K3 * HD) return;
    wih32[idx] = rnd_tf32(Wih[idx]);
    whh32[idx] = rnd_tf32(Whh[idx]);
}

__global__ void count_edges_kernel(const int* __restrict__ dst, int* __restrict__ cnt) {
    int e = blockIdx.x * blockDim.x + threadIdx.x;
    if (e < NE) atomicAdd(&cnt[dst[e]], 1);
}

__global__ void scan_counts_kernel(const int* __restrict__ cnt, int* __restrict__ rowptr,
                                   int* __restrict__ cursor, int n) {
    __shared__ int sh[1024];
    __shared__ int carry;
    int tid = threadIdx.x;
    if (tid == 0) { carry = 0; rowptr[0] = 0; }
    __syncthreads();
    for (int base = 0; base < n; base += 1024) {
        int i = base + tid;
        int v = (i < n) ? cnt[i] : 0;
        sh[tid] = v;
        __syncthreads();
        for (int off = 1; off < 1024; off <<= 1) {
            int t = (tid >= off) ? sh[tid - off] : 0;
            __syncthreads();
            sh[tid] += t;
            __syncthreads();
        }
        int incl = sh[tid];
        int c = carry;
        if (i < n) {
            rowptr[i + 1] = c + incl;
            cursor[i]     = c + incl - v;
        }
        __syncthreads();
        if (tid == 1023) carry = c + sh[1023];
        __syncthreads();
    }
}

__global__ void place_edges_kernel(const int* __restrict__ src, const int* __restrict__ dst,
                                   const int* __restrict__ etype, int* __restrict__ cursor,
                                   int* __restrict__ edges) {
    int e = blockIdx.x * blockDim.x + threadIdx.x;
    if (e >= NE) return;
    int d = dst[e];
    int pos = atomicAdd(&cursor[d], 1);
    edges[pos] = src[e] | (etype[e] << 24);
}

__global__ void goff_kernel(const int* __restrict__ graph_id, int* __restrict__ goff) {
    int g = threadIdx.x;
    if (g > NG) return;
    if (g == NG) { goff[NG] = NN; return; }
    int lo = 0, hi = NN;
    while (lo < hi) {
        int mid = (lo + hi) >> 1;
        if (graph_id[mid] < g) lo = mid + 1; else hi = mid;
    }
    goff[g] = lo;
}

// embedding gather: full-precision h + rounded copy h32
__global__ void embed_kernel(const int* __restrict__ text_idx, const float* __restrict__ emb,
                             float* __restrict__ h, float* __restrict__ h32) {
    int idx = blockIdx.x * blockDim.x + threadIdx.x;
    if (idx >= NN * HD) return;
    int n = idx >> 7, c = idx & 127;
    float v = emb[(size_t)text_idx[n] * HD + c];
    h[idx] = v;
    h32[idx] = rnd_tf32(v);
}

__global__ void mean_kernel(const float* __restrict__ h, const int* __restrict__ goff,
                            float* __restrict__ agg, int slot) {
    int g = blockIdx.x;
    int c = threadIdx.x; // 128
    int s = goff[g], e = goff[g + 1];
    float a0 = 0.f, a1 = 0.f, a2 = 0.f, a3 = 0.f;
    int r = s;
    for (; r + 4 <= e; r += 4) {
        a0 += h[(size_t)(r + 0) * HD + c];
        a1 += h[(size_t)(r + 1) * HD + c];
        a2 += h[(size_t)(r + 2) * HD + c];
        a3 += h[(size_t)(r + 3) * HD + c];
    }
    for (; r < e; ++r) a0 += h[(size_t)r * HD + c];
    float acc = (a0 + a1) + (a2 + a3);
    float cntf = (float)((e - s) > 0 ? (e - s) : 1);
    agg[g * K3 + slot * HD + c] = acc / cntf;
}

// one warp per dst node: per-etype sums of (full-precision) h -> S pre-rounded to tf32
__global__ void aggregate_kernel(const float* __restrict__ h, const int* __restrict__ rowptr,
                                 const int* __restrict__ edges, float* __restrict__ S,
                                 float* __restrict__ deg) {
    int warp = (blockIdx.x * blockDim.x + threadIdx.x) >> 5;
    int lane = threadIdx.x & 31;
    if (warp >= NN) return;
    int s = rowptr[warp], e = rowptr[warp + 1];
    float4 a0 = {0,0,0,0}, a1 = {0,0,0,0}, a2 = {0,0,0,0};
    int c0 = 0, c1 = 0, c2 = 0;
    const float4* h4 = (const float4*)h;
    for (int i = s; i < e; ++i) {
        int p = edges[i];
        int srcn = p & 0xFFFFFF;
        int t = p >> 24;
        float4 v = h4[(size_t)srcn * 32 + lane];
        if (t == 0)      { f4add(a0, v); c0++; }
        else if (t == 1) { f4add(a1, v); c1++; }
        else             { f4add(a2, v); c2++; }
    }
    uint4* S4 = (uint4*)S;
    size_t base = (size_t)warp * 96;
    S4[base + lane]      = make_uint4(cvt_tf32(a0.x), cvt_tf32(a0.y), cvt_tf32(a0.z), cvt_tf32(a0.w));
    S4[base + 32 + lane] = make_uint4(cvt_tf32(a1.x), cvt_tf32(a1.y), cvt_tf32(a1.z), cvt_tf32(a1.w));
    S4[base + 64 + lane] = make_uint4(cvt_tf32(a2.x), cvt_tf32(a2.y), cvt_tf32(a2.z), cvt_tf32(a2.w));
    if (lane == 0) {
        deg[(size_t)warp * 3 + 0] = (float)c0;
        deg[(size_t)warp * 3 + 1] = (float)c1;
        deg[(size_t)warp * 3 + 2] = (float)c2;
    }
}

// ---------------- TF32 GEMM: inputs are PRE-ROUNDED tf32 bits; smem pass-through --------
#define GEMM_SMEM_BYTES (2 * 128 * 36 * 2 * 4)

// C[m][j] = sum_k A[m][k]*B[j][k]; mode2 epilogue (+deg-weighted bl3), output ROUNDED
__global__ __launch_bounds__(256) void tf32gemm_abt_kernel(
    const float* __restrict__ A, const float* __restrict__ B, float* __restrict__ C,
    int M, int K, int J,
    const float* __restrict__ deg, const float* __restrict__ bl3)
{
    extern __shared__ unsigned sm[];
    unsigned* AsBase = sm;
    unsigned* BsBase = sm + 2 * 128 * 36;

    const int tid = threadIdx.x;
    const int warp = tid >> 5;
    const int lane = tid & 31;
    const int g    = lane >> 2;
    const int tg   = lane & 3;
    const int wm   = (warp >> 2) * 64;
    const int wn   = (warp & 3) * 32;
    const int m0   = blockIdx.x * 128;
    const int j0   = blockIdx.y * 128;

    float acc[4][4][4];
#pragma unroll
    for (int mi = 0; mi < 4; ++mi)
#pragma unroll
        for (int ni = 0; ni < 4; ++ni)
#pragma unroll
            for (int q = 0; q < 4; ++q) acc[mi][ni][q] = 0.f;

    uint4 rA[4], rB[4];
    const int numT = K >> 5;

    auto GLOAD = [&](int t) {
        int k0 = t << 5;
#pragma unroll
        for (int u = 0; u < 4; ++u) {
            int f  = tid + u * 256;
            int r  = f >> 3;
            int kq = (f & 7) << 2;
            int gm = m0 + r;
            rA[u] = (gm < M) ? *(const uint4*)(A + (size_t)gm * K + k0 + kq)
                             : make_uint4(0u, 0u, 0u, 0u);
            rB[u] = *(const uint4*)(B + (size_t)(j0 + r) * K + k0 + kq);
        }
    };
    auto SSTORE = [&](int buf) {
        unsigned* a = AsBase + buf * (128 * 36);
        unsigned* b = BsBase + buf * (128 * 36);
#pragma unroll
        for (int u = 0; u < 4; ++u) {
            int f  = tid + u * 256;
            int r  = f >> 3;
            int kq = (f & 7) << 2;
            *(uint4*)(a + r * 36 + kq) = rA[u];
            *(uint4*)(b + r * 36 + kq) = rB[u];
        }
    };
    auto COMP = [&](int buf) {
        const unsigned* a = AsBase + buf * (128 * 36);
        const unsigned* b = BsBase + buf * (128 * 36);
#pragma unroll
        for (int kk = 0; kk < 32; kk += 8) {
            unsigned af[4][4], bf[4][2];
#pragma unroll
            for (int mi = 0; mi < 4; ++mi) {
                int r = wm + mi * 16 + g;
                af[mi][0] = a[r * 36 + kk + tg];
                af[mi][1] = a[(r + 8) * 36 + kk + tg];
                af[mi][2] = a[r * 36 + kk + tg + 4];
                af[mi][3] = a[(r + 8) * 36 + kk + tg + 4];
            }
#pragma unroll
            for (int ni = 0; ni < 4; ++ni) {
                int c = wn + ni * 8 + g;
                bf[ni][0] = b[c * 36 + kk + tg];
                bf[ni][1] = b[c * 36 + kk + tg + 4];
            }
#pragma unroll
            for (int mi = 0; mi < 4; ++mi)
#pragma unroll
                for (int ni = 0; ni < 4; ++ni) {
                    asm volatile(
                        "mma.sync.aligned.m16n8k8.row.col.f32.tf32.tf32.f32 "
                        "{%0,%1,%2,%3}, {%4,%5,%6,%7}, {%8,%9}, {%0,%1,%2,%3};"
                        : "+f"(acc[mi][ni][0]), "+f"(acc[mi][ni][1]),
                          "+f"(acc[mi][ni][2]), "+f"(acc[mi][ni][3])
                        : "r"(af[mi][0]), "r"(af[mi][1]), "r"(af[mi][2]), "r"(af[mi][3]),
                          "r"(bf[ni][0]), "r"(bf[ni][1]));
                }
        }
    };

    GLOAD(0); SSTORE(0); __syncthreads();
    for (int t = 0; t < numT; ++t) {
        if (t + 1 < numT) GLOAD(t + 1);
        COMP(t & 1);
        if (t + 1 < numT) SSTORE((t + 1) & 1);
        __syncthreads();
    }

#pragma unroll
    for (int mi = 0; mi < 4; ++mi) {
        int r0 = m0 + wm + mi * 16 + g;
        int r1 = r0 + 8;
        float d00 = 0.f, d01 = 0.f, d02 = 0.f, d10 = 0.f, d11 = 0.f, d12 = 0.f;
        if (r0 < M) { d00 = deg[(size_t)r0 * 3]; d01 = deg[(size_t)r0 * 3 + 1]; d02 = deg[(size_t)r0 * 3 + 2]; }
        if (r1 < M) { d10 = deg[(size_t)r1 * 3]; d11 = deg[(size_t)r1 * 3 + 1]; d12 = deg[(size_t)r1 * 3 + 2]; }
#pragma unroll
        for (int ni = 0; ni < 4; ++ni) {
            int cl = wn + ni * 8 + tg * 2;
            int c  = j0 + cl;
            float e00 = bl3[cl],       e01 = bl3[cl + 1];
            float e10 = bl3[128 + cl], e11 = bl3[129 + cl];
            float e20 = bl3[256 + cl], e21 = bl3[257 + cl];
            float v00 = acc[mi][ni][0] + d00 * e00 + d01 * e10 + d02 * e20;
            float v01 = acc[mi][ni][1] + d00 * e01 + d01 * e11 + d02 * e21;
            float v10 = acc[mi][ni][2] + d10 * e00 + d11 * e10 + d12 * e20;
            float v11 = acc[mi][ni][3] + d10 * e01 + d11 * e11 + d12 * e21;
            // a is consumed only by the next GEMM -> store pre-rounded
            if (r0 < M) *(float2*)(C + (size_t)r0 * J + c) = make_float2(rnd_tf32(v00), rnd_tf32(v01));
            if (r1 < M) *(float2*)(C + (size_t)r1 * J + c) = make_float2(rnd_tf32(v10), rnd_tf32(v11));
        }
    }
}

// ---------------- paired GEMM (gi-chunk + gh-chunk into one tile) + partial gates --------
// grid (391, 3): chunk 0 -> r; chunk 1 -> z; chunk 2 -> i_n and h_n. Inputs pre-rounded.
__global__ __launch_bounds__(256) void gemm_pair_kernel(
    const float* __restrict__ abuf, const float* __restrict__ hbuf,
    const float* __restrict__ W_ih_l, const float* __restrict__ W_hh_l,
    const float* __restrict__ b_ih_l, const float* __restrict__ b_hh_l,
    float* __restrict__ rbuf, float* __restrict__ zbuf,
    float* __restrict__ inbuf, float* __restrict__ hnbuf)
{
    extern __shared__ unsigned sm[];
    unsigned* AsBase = sm;
    unsigned* BsBase = sm + 2 * 128 * 36;

    const int tid  = threadIdx.x;
    const int warp = tid >> 5;
    const int lane = tid & 31;
    const int g    = lane >> 2;
    const int tg   = lane & 3;
    const int wm   = (warp >> 2) * 64;
    const int wn   = (warp & 3) * 32;
    const int m0   = blockIdx.x * 128;
    const int chunk = blockIdx.y;

    float acc[4][4][4];
    uint4 rA[4], rB[4];

    auto CLEAR = [&]() {
#pragma unroll
        for (int mi = 0; mi < 4; ++mi)
#pragma unroll
            for (int ni = 0; ni < 4; ++ni)
#pragma unroll
                for (int q = 0; q < 4; ++q) acc[mi][ni][q] = 0.f;
    };
    auto GLOAD = [&](const float* __restrict__ A, const float* __restrict__ B, int t) {
        int k0 = t << 5;
#pragma unroll
        for (int u = 0; u < 4; ++u) {
            int f  = tid + u * 256;
            int r  = f >> 3;
            int kq = (f & 7) << 2;
            int gm = m0 + r;
            rA[u] = (gm < NN) ? *(const uint4*)(A + (size_t)gm * HD + k0 + kq)
                              : make_uint4(0u, 0u, 0u, 0u);
            rB[u] = *(const uint4*)(B + (size_t)r * HD + k0 + kq);
        }
    };
    auto SSTORE = [&](int buf) {
        unsigned* a = AsBase + buf * (128 * 36);
        unsigned* b = BsBase + buf * (128 * 36);
#pragma unroll
        for (int u = 0; u < 4; ++u) {
            int f  = tid + u * 256;
            int r  = f >> 3;
            int kq = (f & 7) << 2;
            *(uint4*)(a + r * 36 + kq) = rA[u];
            *(uint4*)(b + r * 36 + kq) = rB[u];
        }
    };
    auto COMP = [&](int buf) {
        const unsigned* a = AsBase + buf * (128 * 36);
        const unsigned* b = BsBase + buf * (128 * 36);
#pragma unroll
        for (int kk = 0; kk < 32; kk += 8) {
            unsigned af[4][4], bf[4][2];
#pragma unroll
            for (int mi = 0; mi < 4; ++mi) {
                int r = wm + mi * 16 + g;
                af[mi][0] = a[r * 36 + kk + tg];
                af[mi][1] = a[(r + 8) * 36 + kk + tg];
                af[mi][2] = a[r * 36 + kk + tg + 4];
                af[mi][3] = a[(r + 8) * 36 + kk + tg + 4];
            }
#pragma unroll
            for (int ni = 0; ni < 4; ++ni) {
                int c = wn + ni * 8 + g;
                bf[ni][0] = b[c * 36 + kk + tg];
                bf[ni][1] = b[c * 36 + kk + tg + 4];
            }
#pragma unroll
            for (int mi = 0; mi < 4; ++mi)
#pragma unroll
                for (int ni = 0; ni < 4; ++ni) {
                    asm volatile(
                        "mma.sync.aligned.m16n8k8.row.col.f32.tf32.tf32.f32 "
                        "{%0,%1,%2,%3}, {%4,%5,%6,%7}, {%8,%9}, {%0,%1,%2,%3};"
                        : "+f"(acc[mi][ni][0]), "+f"(acc[mi][ni][1]),
                          "+f"(acc[mi][ni][2]), "+f"(acc[mi][ni][3])
                        : "r"(af[mi][0]), "r"(af[mi][1]), "r"(af[mi][2]), "r"(af[mi][3]),
                          "r"(bf[ni][0]), "r"(bf[ni][1]));
                }
        }
    };
    auto RUN = [&](const float* __restrict__ A, const float* __restrict__ B) {
        GLOAD(A, B, 0); SSTORE(0); __syncthreads();
#pragma unroll
        for (int t = 0; t < 4; ++t) {
            if (t + 1 < 4) GLOAD(A, B, t + 1);
            COMP(t & 1);
            if (t + 1 < 4) SSTORE((t + 1) & 1);
            __syncthreads();
        }
    };
    auto STORE_EPI = [&](float* __restrict__ out, const float* __restrict__ bias0,
                         const float* __restrict__ bias1, bool sig) {
#pragma unroll
        for (int mi = 0; mi < 4; ++mi) {
            int r0 = m0 + wm + mi * 16 + g;
            int r1 = r0 + 8;
#pragma unroll
            for (int ni = 0; ni < 4; ++ni) {
                int cl = wn + ni * 8 + tg * 2;
                float bb0 = bias0[cl], bb1 = bias0[cl + 1];
                if (bias1) { bb0 += bias1[cl]; bb1 += bias1[cl + 1]; }
                float v00 = acc[mi][ni][0] + bb0, v01 = acc[mi][ni][1] + bb1;
                float v10 = acc[mi][ni][2] + bb0, v11 = acc[mi][ni][3] + bb1;
                if (sig) {
                    v00 = 1.f / (1.f + expf(-v00));
                    v01 = 1.f / (1.f + expf(-v01));
                    v10 = 1.f / (1.f + expf(-v10));
                    v11 = 1.f / (1.f + expf(-v11));
                }
                if (r0 < NN) *(float2*)(out + (size_t)r0 * HD + cl) = make_float2(v00, v01);
                if (r1 < NN) *(float2*)(out + (size_t)r1 * HD + cl) = make_float2(v10, v11);
            }
        }
    };

    if (chunk < 2) {
        CLEAR();
        RUN(abuf, W_ih_l + (size_t)chunk * 128 * HD);
        RUN(hbuf, W_hh_l + (size_t)chunk * 128 * HD);
        STORE_EPI(chunk == 0 ? rbuf : zbuf,
                  b_ih_l + chunk * 128, b_hh_l + chunk * 128, true);
    } else {
        CLEAR();
        RUN(abuf, W_ih_l + (size_t)256 * HD);
        STORE_EPI(inbuf, b_ih_l + 256, nullptr, false);
        CLEAR();
        RUN(hbuf, W_hh_l + (size_t)256 * HD);
        STORE_EPI(hnbuf, b_hh_l + 256, nullptr, false);
    }
}

// ---------------- final gates: h = (1-z)*tanh(i_n + r*h_n) + z*h; also h32 -------------
__global__ void gates_kernel(const float* __restrict__ rbuf, const float* __restrict__ zbuf,
                             const float* __restrict__ inbuf, const float* __restrict__ hnbuf,
                             float* __restrict__ h, float* __restrict__ h32) {
    int idx = blockIdx.x * blockDim.x + threadIdx.x;
    if (idx >= NN * HD) return;
    float r = rbuf[idx], z = zbuf[idx];
    float nc = tanhf(inbuf[idx] + r * hnbuf[idx]);
    float nh = (1.f - z) * nc + z * h[idx];
    h[idx] = nh;
    h32[idx] = rnd_tf32(nh);
}

// ---------------- head ----------------
__global__ void head_kernel(const float* __restrict__ agg, const float* __restrict__ W1,
                            const float* __restrict__ b1, const float* __restrict__ W2,
                            const float* __restrict__ b2, float* __restrict__ out,
                            int out_size) {
    int g = blockIdx.x;
    int o = threadIdx.x; // 128
    __shared__ float sa[K3];
    __shared__ float sx[HD];
    for (int k = o; k < K3; k += HD) sa[k] = agg[g * K3 + k];
    __syncthreads();
    float acc = b1[o];
    for (int k = 0; k < K3; ++k) acc += sa[k] * W1[k * HD + o];
    acc = fmaxf(acc, 0.f);
    sx[o] = acc * W2[o];
    __syncthreads();
    for (int st = 64; st > 0; st >>= 1) {
        if (o < st) sx[o] += sx[o + st];
        __syncthreads();
    }
    if (o == 0 && g < out_size) out[g] = sx[0] + b2[0];
    for (int k = o; k < K3; k += HD) {
        int oi = NG + g * K3 + k;
        if (oi < out_size) out[oi] = sa[k];
    }
}

// ---------------- host launch ----------------
extern "C" void kernel_launch(void* const* d_in, const int* in_sizes, int n_in,
                              void* d_out, int out_size) {
    const int*   text_idx = (const int*)d_in[0];
    const int*   src      = (const int*)d_in[1];
    const int*   dst      = (const int*)d_in[2];
    const int*   etype    = (const int*)d_in[3];
    const int*   graph_id = (const int*)d_in[4];
    const float* emb      = (const float*)d_in[5];
    const float* Wl       = (const float*)d_in[6];
    const float* bl       = (const float*)d_in[7];
    const float* W_ih     = (const float*)d_in[8];
    const float* W_hh     = (const float*)d_in[9];
    const float* b_ih     = (const float*)d_in[10];
    const float* b_hh     = (const float*)d_in[11];
    const float* W1       = (const float*)d_in[12];
    const float* b1       = (const float*)d_in[13];
    const float* W2       = (const float*)d_in[14];
    const float* b2       = (const float*)d_in[15];
    float* out = (float*)d_out;

    float *h, *S, *a, *gi, *gh, *deg, *wcatT, *wih32, *whh32, *agg;
    int *cnt, *rowptr, *cursor, *edges, *goff;
    cudaGetSymbolAddress((void**)&h,      d_h);
    cudaGetSymbolAddress((void**)&S,      d_S);
    cudaGetSymbolAddress((void**)&a,      d_a);
    cudaGetSymbolAddress((void**)&gi,     d_gi);
    cudaGetSymbolAddress((void**)&gh,     d_gh);
    cudaGetSymbolAddress((void**)&deg,    d_deg);
    cudaGetSymbolAddress((void**)&wcatT,  d_wcatT);
    cudaGetSymbolAddress((void**)&wih32,  d_wih32);
    cudaGetSymbolAddress((void**)&whh32,  d_whh32);
    cudaGetSymbolAddress((void**)&agg,    d_agg);
    cudaGetSymbolAddress((void**)&cnt,    d_cnt);
    cudaGetSymbolAddress((void**)&rowptr, d_rowptr);
    cudaGetSymbolAddress((void**)&cursor, d_cursor);
    cudaGetSymbolAddress((void**)&edges,  d_edges);
    cudaGetSymbolAddress((void**)&goff,   d_goff);

    // gate planes (reuse gi/gh scratch); h32 = rounded h copy
    float* rbuf  = gi;
    float* zbuf  = gi + (size_t)NN * HD;
    float* inbuf = gi + (size_t)2 * NN * HD;
    float* hnbuf = gh;
    float* h32   = gh + (size_t)NN * HD;

    static bool attr_set = false;
    if (!attr_set) {
        cudaFuncSetAttribute(tf32gemm_abt_kernel,
                             cudaFuncAttributeMaxDynamicSharedMemorySize, GEMM_SMEM_BYTES);
        cudaFuncSetAttribute(gemm_pair_kernel,
                             cudaFuncAttributeMaxDynamicSharedMemorySize, GEMM_SMEM_BYTES);
        attr_set = true;
    }

    // ---- setup ----
    transpose_wl_kernel<<<(2 * 3 * 128 * 128 + 255) / 256, 256>>>(Wl, wcatT);
    round_w_kernel<<<(2 * K3 * HD + 255) / 256, 256>>>(W_ih, W_hh, wih32, whh32);
    cudaMemsetAsync(cnt, 0, NN * sizeof(int));
    count_edges_kernel<<<(NE + 255) / 256, 256>>>(dst, cnt);
    scan_counts_kernel<<<1, 1024>>>(cnt, rowptr, cursor, NN);
    place_edges_kernel<<<(NE + 255) / 256, 256>>>(src, dst, etype, cursor, edges);
    goff_kernel<<<1, NG + 1>>>(graph_id, goff);

    embed_kernel<<<(NN * HD + 255) / 256, 256>>>(text_idx, emb, h, h32);
    mean_kernel<<<NG, HD>>>(h, goff, agg, 0);

    const dim3 g1((NN + 127) / 128, 1);
    const dim3 gp((NN + 127) / 128, 3);

    for (int l = 0; l < NLAYERS; ++l) {
        for (int s = 0; s < NSTEPS; ++s) {
            aggregate_kernel<<<(NN * 32 + 255) / 256, 256>>>(h, rowptr, edges, S, deg);
            // a = S @ WcatT^T + deg-weighted etype bias (output pre-rounded)
            tf32gemm_abt_kernel<<<g1, 256, GEMM_SMEM_BYTES>>>(
                S, wcatT + (size_t)l * HD * K3, a,
                NN, K3, HD, deg, bl + l * K3);
            // paired gi/gh GEMMs with partial gate fusion (A inputs pre-rounded)
            gemm_pair_kernel<<<gp, 256, GEMM_SMEM_BYTES>>>(
                a, h32,
                wih32 + (size_t)l * K3 * HD, whh32 + (size_t)l * K3 * HD,
                b_ih + l * K3, b_hh + l * K3,
                rbuf, zbuf, inbuf, hnbuf);
            gates_kernel<<<(NN * HD + 255) / 256, 256>>>(rbuf, zbuf, inbuf, hnbuf, h, h32);
        }
        mean_kernel<<<NG, HD>>>(h, goff, agg, l + 1);
    }

    head_kernel<<<NG, HD>>>(agg, W1, b1, W2, b2, out, out_size);
}

// round 10
// speedup vs baseline: 1.2880x; 1.0913x over previous
#include <cuda_runtime.h>
#include <math.h>
#include <stdint.h>

// ---------------- problem constants ----------------
#define NN 50000         // nodes
#define NE 600000        // edges
#define HD 128           // hidden
#define NG 64            // graphs
#define K3 384           // 3*H
#define NLAYERS 2
#define NSTEPS 2
#define NSTAGE 3

// ---------------- device scratch (no allocs allowed) ----------------
__device__ float d_h[(size_t)NN * HD];
__device__ float d_S[(size_t)NN * K3];
__device__ float d_a[(size_t)NN * HD];
__device__ float d_gi[(size_t)NN * K3];   // planes: r | z | i_n
__device__ float d_gh[(size_t)NN * K3];   // planes: h_n | h32 (rounded h copy)
__device__ float d_deg[(size_t)NN * 3];
__device__ int   d_cnt[NN];
__device__ int   d_rowptr[NN + 1];
__device__ int   d_cursor[NN];
__device__ int   d_edges[NE];
__device__ int   d_goff[NG + 1];
__device__ float d_wcatT[2 * HD * K3];   // per layer: [128 out][384 k], tf32-rounded
__device__ float d_wih32[2 * K3 * HD];   // tf32-rounded W_ih
__device__ float d_whh32[2 * K3 * HD];   // tf32-rounded W_hh
__device__ float d_agg[NG * K3];

__device__ __forceinline__ unsigned cvt_tf32(float x) {
    unsigned r;
    asm("cvt.rna.tf32.f32 %0, %1;" : "=r"(r) : "f"(x));
    return r;
}
__device__ __forceinline__ float rnd_tf32(float x) {
    return __uint_as_float(cvt_tf32(x));
}
__device__ __forceinline__ void f4add(float4& a, const float4& b) {
    a.x += b.x; a.y += b.y; a.z += b.z; a.w += b.w;
}
__device__ __forceinline__ void cp_async16(unsigned saddr, const void* gptr, int szbytes) {
    asm volatile("cp.async.cg.shared.global [%0], [%1], 16, %2;"
                 :: "r"(saddr), "l"(gptr), "r"(szbytes));
}
#define CP_COMMIT() asm volatile("cp.async.commit_group;")
#define CP_WAIT(n)  asm volatile("cp.async.wait_group %0;" :: "n"(n))

// ---------------- small setup kernels ----------------

__global__ void transpose_wl_kernel(const float* __restrict__ Wl, float* __restrict__ wcatT) {
    int idx = blockIdx.x * blockDim.x + threadIdx.x;
    if (idx >= 2 * 3 * 128 * 128) return;
    int o  = idx & 127;
    int hh = (idx >> 7) & 127;
    int lt = idx >> 14;
    int t  = lt % 3;
    int l  = lt / 3;
    wcatT[(size_t)l * HD * K3 + (size_t)o * K3 + t * 128 + hh] = rnd_tf32(Wl[idx]);
}

__global__ void round_w_kernel(const float* __restrict__ Wih, const float* __restrict__ Whh,
                               float* __restrict__ wih32, float* __restrict__ whh32) {
    int idx = blockIdx.x * blockDim.x + threadIdx.x;
    if (idx >= 2 * K3 * HD) return;
    wih32[idx] = rnd_tf32(Wih[idx]);
    whh32[idx] = rnd_tf32(Whh[idx]);
}

__global__ void count_edges_kernel(const int* __restrict__ dst, int* __restrict__ cnt) {
    int e = blockIdx.x * blockDim.x + threadIdx.x;
    if (e < NE) atomicAdd(&cnt[dst[e]], 1);
}

// fast single-block scan: each thread owns a contiguous chunk, shuffle-scan the partials
__global__ void scan_counts_kernel(const int* __restrict__ cnt, int* __restrict__ rowptr,
                                   int* __restrict__ cursor, int n) {
    const int CH = (n + 1023) / 1024;   // 49
    int tid = threadIdx.x;
    int s = tid * CH;
    int e = s + CH < n ? s + CH : n;
    int sum = 0;
    for (int i = s; i < e; ++i) sum += cnt[i];

    __shared__ int warpsums[32];
    int lane = tid & 31, wid = tid >> 5;
    int v = sum;
#pragma unroll
    for (int off = 1; off < 32; off <<= 1) {
        int t = __shfl_up_sync(0xFFFFFFFFu, v, off);
        if (lane >= off) v += t;
    }
    if (lane == 31) warpsums[wid] = v;
    __syncthreads();
    if (wid == 0) {
        int w = warpsums[lane];
#pragma unroll
        for (int off = 1; off < 32; off <<= 1) {
            int t = __shfl_up_sync(0xFFFFFFFFu, w, off);
            if (lane >= off) w += t;
        }
        warpsums[lane] = w;
    }
    __syncthreads();
    int excl = (v - sum) + (wid > 0 ? warpsums[wid - 1] : 0);
    int run = excl;
    for (int i = s; i < e; ++i) {
        int c = cnt[i];
        cursor[i] = run;
        run += c;
        rowptr[i + 1] = run;
    }
    if (tid == 0) rowptr[0] = 0;
}

__global__ void place_edges_kernel(const int* __restrict__ src, const int* __restrict__ dst,
                                   const int* __restrict__ etype, int* __restrict__ cursor,
                                   int* __restrict__ edges) {
    int e = blockIdx.x * blockDim.x + threadIdx.x;
    if (e >= NE) return;
    int d = dst[e];
    int pos = atomicAdd(&cursor[d], 1);
    edges[pos] = src[e] | (etype[e] << 24);
}

__global__ void goff_kernel(const int* __restrict__ graph_id, int* __restrict__ goff) {
    int g = threadIdx.x;
    if (g > NG) return;
    if (g == NG) { goff[NG] = NN; return; }
    int lo = 0, hi = NN;
    while (lo < hi) {
        int mid = (lo + hi) >> 1;
        if (graph_id[mid] < g) lo = mid + 1; else hi = mid;
    }
    goff[g] = lo;
}

__global__ void embed_kernel(const int* __restrict__ text_idx, const float* __restrict__ emb,
                             float* __restrict__ h, float* __restrict__ h32) {
    int idx = blockIdx.x * blockDim.x + threadIdx.x;
    if (idx >= NN * HD) return;
    int n = idx >> 7, c = idx & 127;
    float v = emb[(size_t)text_idx[n] * HD + c];
    h[idx] = v;
    h32[idx] = rnd_tf32(v);
}

__global__ void mean_kernel(const float* __restrict__ h, const int* __restrict__ goff,
                            float* __restrict__ agg, int slot) {
    int g = blockIdx.x;
    int c = threadIdx.x; // 128
    int s = goff[g], e = goff[g + 1];
    float a0 = 0.f, a1 = 0.f, a2 = 0.f, a3 = 0.f;
    int r = s;
    for (; r + 4 <= e; r += 4) {
        a0 += h[(size_t)(r + 0) * HD + c];
        a1 += h[(size_t)(r + 1) * HD + c];
        a2 += h[(size_t)(r + 2) * HD + c];
        a3 += h[(size_t)(r + 3) * HD + c];
    }
    for (; r < e; ++r) a0 += h[(size_t)r * HD + c];
    float acc = (a0 + a1) + (a2 + a3);
    float cntf = (float)((e - s) > 0 ? (e - s) : 1);
    agg[g * K3 + slot * HD + c] = acc / cntf;
}

// one warp per dst node: per-etype sums -> S pre-rounded to tf32
__global__ void aggregate_kernel(const float* __restrict__ h, const int* __restrict__ rowptr,
                                 const int* __restrict__ edges, float* __restrict__ S,
                                 float* __restrict__ deg) {
    int warp = (blockIdx.x * blockDim.x + threadIdx.x) >> 5;
    int lane = threadIdx.x & 31;
    if (warp >= NN) return;
    int s = rowptr[warp], e = rowptr[warp + 1];
    float4 a0 = {0,0,0,0}, a1 = {0,0,0,0}, a2 = {0,0,0,0};
    int c0 = 0, c1 = 0, c2 = 0;
    const float4* h4 = (const float4*)h;
    for (int i = s; i < e; ++i) {
        int p = edges[i];
        int srcn = p & 0xFFFFFF;
        int t = p >> 24;
        float4 v = h4[(size_t)srcn * 32 + lane];
        if (t == 0)      { f4add(a0, v); c0++; }
        else if (t == 1) { f4add(a1, v); c1++; }
        else             { f4add(a2, v); c2++; }
    }
    uint4* S4 = (uint4*)S;
    size_t base = (size_t)warp * 96;
    S4[base + lane]      = make_uint4(cvt_tf32(a0.x), cvt_tf32(a0.y), cvt_tf32(a0.z), cvt_tf32(a0.w));
    S4[base + 32 + lane] = make_uint4(cvt_tf32(a1.x), cvt_tf32(a1.y), cvt_tf32(a1.z), cvt_tf32(a1.w));
    S4[base + 64 + lane] = make_uint4(cvt_tf32(a2.x), cvt_tf32(a2.y), cvt_tf32(a2.z), cvt_tf32(a2.w));
    if (lane == 0) {
        deg[(size_t)warp * 3 + 0] = (float)c0;
        deg[(size_t)warp * 3 + 1] = (float)c1;
        deg[(size_t)warp * 3 + 2] = (float)c2;
    }
}

// ---------------- TF32 GEMM, cp.async 3-stage pipeline ----------------
// smem: A stages [NSTAGE][128*36] + B stages [NSTAGE][128*36] (u32, pre-rounded tf32 bits)
#define TILE_U32   (128 * 36)
#define GEMM_SMEM_BYTES (NSTAGE * TILE_U32 * 2 * 4)

// C[m][j] = sum_k A[m][k]*B[j][k]; +deg-weighted bl3 epilogue; output rounded to tf32
__global__ __launch_bounds__(256, 2) void tf32gemm_abt_kernel(
    const float* __restrict__ A, const float* __restrict__ B, float* __restrict__ C,
    int M, int K, int J,
    const float* __restrict__ deg, const float* __restrict__ bl3)
{
    extern __shared__ unsigned sm[];
    unsigned* As = sm;
    unsigned* Bs = sm + NSTAGE * TILE_U32;

    const int tid = threadIdx.x;
    const int warp = tid >> 5;
    const int lane = tid & 31;
    const int g    = lane >> 2;
    const int tg   = lane & 3;
    const int wm   = (warp >> 2) * 64;
    const int wn   = (warp & 3) * 32;
    const int m0   = blockIdx.x * 128;

    float acc[4][4][4];
#pragma unroll
    for (int mi = 0; mi < 4; ++mi)
#pragma unroll
        for (int ni = 0; ni < 4; ++ni)
#pragma unroll
            for (int q = 0; q < 4; ++q) acc[mi][ni][q] = 0.f;

    const int numT = K >> 5;

    auto GLOAD = [&](int stg, int t) {
        int k0 = t << 5;
        unsigned abase = (unsigned)__cvta_generic_to_shared(As + (size_t)stg * TILE_U32);
        unsigned bbase = (unsigned)__cvta_generic_to_shared(Bs + (size_t)stg * TILE_U32);
#pragma unroll
        for (int u = 0; u < 4; ++u) {
            int f  = tid + u * 256;
            int r  = f >> 3;
            int kq = (f & 7) << 2;
            int gm = m0 + r;
            int gmc = gm < M ? gm : (M - 1);
            cp_async16(abase + (unsigned)(r * 36 + kq) * 4,
                       A + (size_t)gmc * K + k0 + kq, gm < M ? 16 : 0);
            cp_async16(bbase + (unsigned)(r * 36 + kq) * 4,
                       B + (size_t)r * K + k0 + kq, 16);
        }
    };
    auto COMP = [&](int stg) {
        const unsigned* a = As + (size_t)stg * TILE_U32;
        const unsigned* b = Bs + (size_t)stg * TILE_U32;
#pragma unroll
        for (int kk = 0; kk < 32; kk += 8) {
            unsigned af[4][4], bf[4][2];
#pragma unroll
            for (int mi = 0; mi < 4; ++mi) {
                int r = wm + mi * 16 + g;
                af[mi][0] = a[r * 36 + kk + tg];
                af[mi][1] = a[(r + 8) * 36 + kk + tg];
                af[mi][2] = a[r * 36 + kk + tg + 4];
                af[mi][3] = a[(r + 8) * 36 + kk + tg + 4];
            }
#pragma unroll
            for (int ni = 0; ni < 4; ++ni) {
                int c = wn + ni * 8 + g;
                bf[ni][0] = b[c * 36 + kk + tg];
                bf[ni][1] = b[c * 36 + kk + tg + 4];
            }
#pragma unroll
            for (int mi = 0; mi < 4; ++mi)
#pragma unroll
                for (int ni = 0; ni < 4; ++ni) {
                    asm volatile(
                        "mma.sync.aligned.m16n8k8.row.col.f32.tf32.tf32.f32 "
                        "{%0,%1,%2,%3}, {%4,%5,%6,%7}, {%8,%9}, {%0,%1,%2,%3};"
                        : "+f"(acc[mi][ni][0]), "+f"(acc[mi][ni][1]),
                          "+f"(acc[mi][ni][2]), "+f"(acc[mi][ni][3])
                        : "r"(af[mi][0]), "r"(af[mi][1]), "r"(af[mi][2]), "r"(af[mi][3]),
                          "r"(bf[ni][0]), "r"(bf[ni][1]));
                }
        }
    };

#pragma unroll
    for (int s = 0; s < NSTAGE - 1; ++s) {
        if (s < numT) GLOAD(s, s);
        CP_COMMIT();
    }
    for (int t = 0; t < numT; ++t) {
        if (t + NSTAGE - 1 < numT) GLOAD((t + NSTAGE - 1) % NSTAGE, t + NSTAGE - 1);
        CP_COMMIT();
        CP_WAIT(NSTAGE - 1);
        __syncthreads();
        COMP(t % NSTAGE);
        __syncthreads();
    }

#pragma unroll
    for (int mi = 0; mi < 4; ++mi) {
        int r0 = m0 + wm + mi * 16 + g;
        int r1 = r0 + 8;
        float d00 = 0.f, d01 = 0.f, d02 = 0.f, d10 = 0.f, d11 = 0.f, d12 = 0.f;
        if (r0 < M) { d00 = deg[(size_t)r0 * 3]; d01 = deg[(size_t)r0 * 3 + 1]; d02 = deg[(size_t)r0 * 3 + 2]; }
        if (r1 < M) { d10 = deg[(size_t)r1 * 3]; d11 = deg[(size_t)r1 * 3 + 1]; d12 = deg[(size_t)r1 * 3 + 2]; }
#pragma unroll
        for (int ni = 0; ni < 4; ++ni) {
            int cl = wn + ni * 8 + tg * 2;
            float e00 = bl3[cl],       e01 = bl3[cl + 1];
            float e10 = bl3[128 + cl], e11 = bl3[129 + cl];
            float e20 = bl3[256 + cl], e21 = bl3[257 + cl];
            float v00 = acc[mi][ni][0] + d00 * e00 + d01 * e10 + d02 * e20;
            float v01 = acc[mi][ni][1] + d00 * e01 + d01 * e11 + d02 * e21;
            float v10 = acc[mi][ni][2] + d10 * e00 + d11 * e10 + d12 * e20;
            float v11 = acc[mi][ni][3] + d10 * e01 + d11 * e11 + d12 * e21;
            if (r0 < M) *(float2*)(C + (size_t)r0 * J + cl) = make_float2(rnd_tf32(v00), rnd_tf32(v01));
            if (r1 < M) *(float2*)(C + (size_t)r1 * J + cl) = make_float2(rnd_tf32(v10), rnd_tf32(v11));
        }
    }
}

// ---------------- paired GEMM + partial gates, cp.async pipeline ----------------
// grid (391, 3): chunk 0 -> r; chunk 1 -> z; chunk 2 -> i_n and h_n.
__global__ __launch_bounds__(256, 2) void gemm_pair_kernel(
    const float* __restrict__ abuf, const float* __restrict__ hbuf,
    const float* __restrict__ W_ih_l, const float* __restrict__ W_hh_l,
    const float* __restrict__ b_ih_l, const float* __restrict__ b_hh_l,
    float* __restrict__ rbuf, float* __restrict__ zbuf,
    float* __restrict__ inbuf, float* __restrict__ hnbuf)
{
    extern __shared__ unsigned sm[];
    unsigned* As = sm;
    unsigned* Bs = sm + NSTAGE * TILE_U32;

    const int tid  = threadIdx.x;
    const int warp = tid >> 5;
    const int lane = tid & 31;
    const int g    = lane >> 2;
    const int tg   = lane & 3;
    const int wm   = (warp >> 2) * 64;
    const int wn   = (warp & 3) * 32;
    const int m0   = blockIdx.x * 128;
    const int chunk = blockIdx.y;

    float acc[4][4][4];

    auto CLEAR = [&]() {
#pragma unroll
        for (int mi = 0; mi < 4; ++mi)
#pragma unroll
            for (int ni = 0; ni < 4; ++ni)
#pragma unroll
                for (int q = 0; q < 4; ++q) acc[mi][ni][q] = 0.f;
    };
    auto GLOAD = [&](const float* __restrict__ A, const float* __restrict__ B, int stg, int t) {
        int k0 = t << 5;
        unsigned abase = (unsigned)__cvta_generic_to_shared(As + (size_t)stg * TILE_U32);
        unsigned bbase = (unsigned)__cvta_generic_to_shared(Bs + (size_t)stg * TILE_U32);
#pragma unroll
        for (int u = 0; u < 4; ++u) {
            int f  = tid + u * 256;
            int r  = f >> 3;
            int kq = (f & 7) << 2;
            int gm = m0 + r;
            int gmc = gm < NN ? gm : (NN - 1);
            cp_async16(abase + (unsigned)(r * 36 + kq) * 4,
                       A + (size_t)gmc * HD + k0 + kq, gm < NN ? 16 : 0);
            cp_async16(bbase + (unsigned)(r * 36 + kq) * 4,
                       B + (size_t)r * HD + k0 + kq, 16);
        }
    };
    auto COMP = [&](int stg) {
        const unsigned* a = As + (size_t)stg * TILE_U32;
        const unsigned* b = Bs + (size_t)stg * TILE_U32;
#pragma unroll
        for (int kk = 0; kk < 32; kk += 8) {
            unsigned af[4][4], bf[4][2];
#pragma unroll
            for (int mi = 0; mi < 4; ++mi) {
                int r = wm + mi * 16 + g;
                af[mi][0] = a[r * 36 + kk + tg];
                af[mi][1] = a[(r + 8) * 36 + kk + tg];
                af[mi][2] = a[r * 36 + kk + tg + 4];
                af[mi][3] = a[(r + 8) * 36 + kk + tg + 4];
            }
#pragma unroll
            for (int ni = 0; ni < 4; ++ni) {
                int c = wn + ni * 8 + g;
                bf[ni][0] = b[c * 36 + kk + tg];
                bf[ni][1] = b[c * 36 + kk + tg + 4];
            }
#pragma unroll
            for (int mi = 0; mi < 4; ++mi)
#pragma unroll
                for (int ni = 0; ni < 4; ++ni) {
                    asm volatile(
                        "mma.sync.aligned.m16n8k8.row.col.f32.tf32.tf32.f32 "
                        "{%0,%1,%2,%3}, {%4,%5,%6,%7}, {%8,%9}, {%0,%1,%2,%3};"
                        : "+f"(acc[mi][ni][0]), "+f"(acc[mi][ni][1]),
                          "+f"(acc[mi][ni][2]), "+f"(acc[mi][ni][3])
                        : "r"(af[mi][0]), "r"(af[mi][1]), "r"(af[mi][2]), "r"(af[mi][3]),
                          "r"(bf[ni][0]), "r"(bf[ni][1]));
                }
        }
    };
    auto RUN = [&](const float* __restrict__ A, const float* __restrict__ B) {
        const int numT = 4;
#pragma unroll
        for (int s = 0; s < NSTAGE - 1; ++s) {
            GLOAD(A, B, s, s);
            CP_COMMIT();
        }
#pragma unroll
        for (int t = 0; t < numT; ++t) {
            if (t + NSTAGE - 1 < numT) GLOAD(A, B, (t + NSTAGE - 1) % NSTAGE, t + NSTAGE - 1);
            CP_COMMIT();
            CP_WAIT(NSTAGE - 1);
            __syncthreads();
            COMP(t % NSTAGE);
            __syncthreads();
        }
    };
    auto STORE_EPI = [&](float* __restrict__ out, const float* __restrict__ bias0,
                         const float* __restrict__ bias1, bool sig) {
#pragma unroll
        for (int mi = 0; mi < 4; ++mi) {
            int r0 = m0 + wm + mi * 16 + g;
            int r1 = r0 + 8;
#pragma unroll
            for (int ni = 0; ni < 4; ++ni) {
                int cl = wn + ni * 8 + tg * 2;
                float bb0 = bias0[cl], bb1 = bias0[cl + 1];
                if (bias1) { bb0 += bias1[cl]; bb1 += bias1[cl + 1]; }
                float v00 = acc[mi][ni][0] + bb0, v01 = acc[mi][ni][1] + bb1;
                float v10 = acc[mi][ni][2] + bb0, v11 = acc[mi][ni][3] + bb1;
                if (sig) {
                    v00 = 1.f / (1.f + expf(-v00));
                    v01 = 1.f / (1.f + expf(-v01));
                    v10 = 1.f / (1.f + expf(-v10));
                    v11 = 1.f / (1.f + expf(-v11));
                }
                if (r0 < NN) *(float2*)(out + (size_t)r0 * HD + cl) = make_float2(v00, v01);
                if (r1 < NN) *(float2*)(out + (size_t)r1 * HD + cl) = make_float2(v10, v11);
            }
        }
    };

    if (chunk < 2) {
        CLEAR();
        RUN(abuf, W_ih_l + (size_t)chunk * 128 * HD);
        RUN(hbuf, W_hh_l + (size_t)chunk * 128 * HD);
        STORE_EPI(chunk == 0 ? rbuf : zbuf,
                  b_ih_l + chunk * 128, b_hh_l + chunk * 128, true);
    } else {
        CLEAR();
        RUN(abuf, W_ih_l + (size_t)256 * HD);
        STORE_EPI(inbuf, b_ih_l + 256, nullptr, false);
        CLEAR();
        RUN(hbuf, W_hh_l + (size_t)256 * HD);
        STORE_EPI(hnbuf, b_hh_l + 256, nullptr, false);
    }
}

// ---------------- final gates: h = (1-z)*tanh(i_n + r*h_n) + z*h; also h32 -------------
__global__ void gates_kernel(const float* __restrict__ rbuf, const float* __restrict__ zbuf,
                             const float* __restrict__ inbuf, const float* __restrict__ hnbuf,
                             float* __restrict__ h, float* __restrict__ h32) {
    int idx = blockIdx.x * blockDim.x + threadIdx.x;
    if (idx >= NN * HD) return;
    float r = rbuf[idx], z = zbuf[idx];
    float nc = tanhf(inbuf[idx] + r * hnbuf[idx]);
    float nh = (1.f - z) * nc + z * h[idx];
    h[idx] = nh;
    h32[idx] = rnd_tf32(nh);
}

// ---------------- head ----------------
__global__ void head_kernel(const float* __restrict__ agg, const float* __restrict__ W1,
                            const float* __restrict__ b1, const float* __restrict__ W2,
                            const float* __restrict__ b2, float* __restrict__ out,
                            int out_size) {
    int g = blockIdx.x;
    int o = threadIdx.x; // 128
    __shared__ float sa[K3];
    __shared__ float sx[HD];
    for (int k = o; k < K3; k += HD) sa[k] = agg[g * K3 + k];
    __syncthreads();
    float acc = b1[o];
    for (int k = 0; k < K3; ++k) acc += sa[k] * W1[k * HD + o];
    acc = fmaxf(acc, 0.f);
    sx[o] = acc * W2[o];
    __syncthreads();
    for (int st = 64; st > 0; st >>= 1) {
        if (o < st) sx[o] += sx[o + st];
        __syncthreads();
    }
    if (o == 0 && g < out_size) out[g] = sx[0] + b2[0];
    for (int k = o; k < K3; k += HD) {
        int oi = NG + g * K3 + k;
        if (oi < out_size) out[oi] = sa[k];
    }
}

// ---------------- host launch ----------------
extern "C" void kernel_launch(void* const* d_in, const int* in_sizes, int n_in,
                              void* d_out, int out_size) {
    const int*   text_idx = (const int*)d_in[0];
    const int*   src      = (const int*)d_in[1];
    const int*   dst      = (const int*)d_in[2];
    const int*   etype    = (const int*)d_in[3];
    const int*   graph_id = (const int*)d_in[4];
    const float* emb      = (const float*)d_in[5];
    const float* Wl       = (const float*)d_in[6];
    const float* bl       = (const float*)d_in[7];
    const float* W_ih     = (const float*)d_in[8];
    const float* W_hh     = (const float*)d_in[9];
    const float* b_ih     = (const float*)d_in[10];
    const float* b_hh     = (const float*)d_in[11];
    const float* W1       = (const float*)d_in[12];
    const float* b1       = (const float*)d_in[13];
    const float* W2       = (const float*)d_in[14];
    const float* b2       = (const float*)d_in[15];
    float* out = (float*)d_out;

    float *h, *S, *a, *gi, *gh, *deg, *wcatT, *wih32, *whh32, *agg;
    int *cnt, *rowptr, *cursor, *edges, *goff;
    cudaGetSymbolAddress((void**)&h,      d_h);
    cudaGetSymbolAddress((void**)&S,      d_S);
    cudaGetSymbolAddress((void**)&a,      d_a);
    cudaGetSymbolAddress((void**)&gi,     d_gi);
    cudaGetSymbolAddress((void**)&gh,     d_gh);
    cudaGetSymbolAddress((void**)&deg,    d_deg);
    cudaGetSymbolAddress((void**)&wcatT,  d_wcatT);
    cudaGetSymbolAddress((void**)&wih32,  d_wih32);
    cudaGetSymbolAddress((void**)&whh32,  d_whh32);
    cudaGetSymbolAddress((void**)&agg,    d_agg);
    cudaGetSymbolAddress((void**)&cnt,    d_cnt);
    cudaGetSymbolAddress((void**)&rowptr, d_rowptr);
    cudaGetSymbolAddress((void**)&cursor, d_cursor);
    cudaGetSymbolAddress((void**)&edges,  d_edges);
    cudaGetSymbolAddress((void**)&goff,   d_goff);

    float* rbuf  = gi;
    float* zbuf  = gi + (size_t)NN * HD;
    float* inbuf = gi + (size_t)2 * NN * HD;
    float* hnbuf = gh;
    float* h32   = gh + (size_t)NN * HD;

    static bool attr_set = false;
    if (!attr_set) {
        cudaFuncSetAttribute(tf32gemm_abt_kernel,
                             cudaFuncAttributeMaxDynamicSharedMemorySize, GEMM_SMEM_BYTES);
        cudaFuncSetAttribute(gemm_pair_kernel,
                             cudaFuncAttributeMaxDynamicSharedMemorySize, GEMM_SMEM_BYTES);
        attr_set = true;
    }

    // ---- setup ----
    transpose_wl_kernel<<<(2 * 3 * 128 * 128 + 255) / 256, 256>>>(Wl, wcatT);
    round_w_kernel<<<(2 * K3 * HD + 255) / 256, 256>>>(W_ih, W_hh, wih32, whh32);
    cudaMemsetAsync(cnt, 0, NN * sizeof(int));
    count_edges_kernel<<<(NE + 255) / 256, 256>>>(dst, cnt);
    scan_counts_kernel<<<1, 1024>>>(cnt, rowptr, cursor, NN);
    place_edges_kernel<<<(NE + 255) / 256, 256>>>(src, dst, etype, cursor, edges);
    goff_kernel<<<1, NG + 1>>>(graph_id, goff);

    embed_kernel<<<(NN * HD + 255) / 256, 256>>>(text_idx, emb, h, h32);
    mean_kernel<<<NG, HD>>>(h, goff, agg, 0);

    const dim3 g1((NN + 127) / 128, 1);
    const dim3 gp((NN + 127) / 128, 3);

    for (int l = 0; l < NLAYERS; ++l) {
        for (int s = 0; s < NSTEPS; ++s) {
            aggregate_kernel<<<(NN * 32 + 255) / 256, 256>>>(h, rowptr, edges, S, deg);
            tf32gemm_abt_kernel<<<g1, 256, GEMM_SMEM_BYTES>>>(
                S, wcatT + (size_t)l * HD * K3, a,
                NN, K3, HD, deg, bl + l * K3);
            gemm_pair_kernel<<<gp, 256, GEMM_SMEM_BYTES>>>(
                a, h32,
                wih32 + (size_t)l * K3 * HD, whh32 + (size_t)l * K3 * HD,
                b_ih + l * K3, b_hh + l * K3,
                rbuf, zbuf, inbuf, hnbuf);
            gates_kernel<<<(NN * HD + 255) / 256, 256>>>(rbuf, zbuf, inbuf, hnbuf, h, h32);
        }
        mean_kernel<<<NG, HD>>>(h, goff, agg, l + 1);
    }

    head_kernel<<<NG, HD>>>(agg, W1, b1, W2, b2, out, out_size);
}